// round 8
// baseline (speedup 1.0000x reference)
#include <cuda_runtime.h>
#include <cuda_bf16.h>
#include <cstdint>

#define N_NODES 10000
#define N_PAD   10112   /* 79 * 128 */
#define D 512
#define KP 1536         /* interleaved K' = 3*D */
#define EPS 1e-5f
#define NLAYERS 3
#define E_MAX 262144

typedef __nv_bfloat16 bf16;

// ---------------- scratch (static device globals; no allocs) ----------------
__device__ float g_xa[N_NODES * D];    // layer ping
__device__ float g_xb[N_NODES * D];    // layer pong
__device__ bf16  g_Aint[N_PAD * KP];   // [Ahi | Ahi | Alo] (pad rows stay 0)
__device__ bf16  g_Wint[NLAYERS * D * KP];  // W^T' = [Whi | Wlo | Whi]
__device__ float g_outdeg[N_NODES];
__device__ int   g_indeg_i[N_NODES];
__device__ float g_srcnorm[N_NODES];
__device__ float g_dstnorm[N_NODES];
__device__ float g_s0[N_NODES];        // sum of srcnorm over in-neighbors
__device__ float g_sum[D];
__device__ float g_sumsq[D];
__device__ int   g_csr_off[N_NODES + 1];
__device__ int   g_cursor[N_NODES];
__device__ int   g_esrc[E_MAX];
__device__ int   g_is64;

// ---------------- PTX helpers ----------------
__device__ __forceinline__ uint32_t smem_u32(const void* p) {
    uint32_t a;
    asm("{ .reg .u64 t; cvta.to.shared.u64 t, %1; cvt.u32.u64 %0, t; }" : "=r"(a) : "l"(p));
    return a;
}
#define CP16(s, g) asm volatile("cp.async.cg.shared.global [%0], [%1], 16;" :: "r"(s), "l"(g) : "memory")
#define CP_COMMIT() asm volatile("cp.async.commit_group;" ::: "memory")
#define CP_WAIT2()  asm volatile("cp.async.wait_group 2;" ::: "memory")
#define MMA_BF16(acc, a, b)                                                           \
    asm volatile("mma.sync.aligned.m16n8k16.row.col.f32.bf16.bf16.f32 "               \
        "{%0,%1,%2,%3},{%4,%5,%6,%7},{%8,%9},{%0,%1,%2,%3};"                          \
        : "+f"((acc)[0]), "+f"((acc)[1]), "+f"((acc)[2]), "+f"((acc)[3])              \
        : "r"((a)[0]), "r"((a)[1]), "r"((a)[2]), "r"((a)[3]),                         \
          "r"((b)[0]), "r"((b)[1]))
#define LDSM4(r0, r1, r2, r3, addr)                                                   \
    asm volatile("ldmatrix.sync.aligned.m8n8.x4.shared.b16 {%0,%1,%2,%3}, [%4];"      \
        : "=r"(r0), "=r"(r1), "=r"(r2), "=r"(r3) : "r"(addr))

// ---------------- helpers ----------------
__device__ __forceinline__ int loadIdx(const void* p, int i, int is64) {
    if (is64) return (int)((const long long*)p)[i];
    return ((const int*)p)[i];
}

// ---------------- small kernels ----------------
__global__ void zero_setup_kernel() {
    int i = blockIdx.x * blockDim.x + threadIdx.x;
    if (i < N_NODES) {
        g_outdeg[i] = 0.0f;
        g_indeg_i[i] = 0;
        g_s0[i] = 0.0f;
    }
}
__global__ void zero_sums_kernel() {
    int i = threadIdx.x;        // 512
    g_sum[i] = 0.0f;
    g_sumsq[i] = 0.0f;
}

__global__ void detect_idx_kernel(const void* src) {
    __shared__ int cnt;
    if (threadIdx.x == 0) cnt = 0;
    __syncthreads();
    const int* p = (const int*)src;
    int v = p[2 * threadIdx.x + 1];
    if (v != 0) atomicAdd(&cnt, 1);
    __syncthreads();
    if (threadIdx.x == 0) g_is64 = (cnt == 0) ? 1 : 0;
}

__global__ void degree_kernel(const void* src, const void* dst, int E) {
    int i = blockIdx.x * blockDim.x + threadIdx.x;
    if (i >= E) return;
    int is64 = g_is64;
    int s = loadIdx(src, i, is64);
    int d = loadIdx(dst, i, is64);
    atomicAdd(&g_outdeg[s], 1.0f);
    atomicAdd(&g_indeg_i[d], 1);
}

// single-block scan via warp shuffles (2 barriers) + norms
__global__ void scan_kernel() {
    __shared__ int wsum[32];
    const int CH = 10;
    int t = threadIdx.x;
    int lane = t & 31, warp = t >> 5;
    int base = t * CH;
    int loc[CH];
    int tot = 0;
#pragma unroll
    for (int j = 0; j < CH; j++) {
        int i = base + j;
        int d = (i < N_NODES) ? g_indeg_i[i] : 0;
        loc[j] = tot;
        tot += d;
    }
    // warp inclusive scan of tot
    int inc = tot;
#pragma unroll
    for (int d = 1; d < 32; d <<= 1) {
        int v = __shfl_up_sync(0xFFFFFFFFu, inc, d);
        if (lane >= d) inc += v;
    }
    if (lane == 31) wsum[warp] = inc;
    __syncthreads();
    if (warp == 0) {
        int w = wsum[lane];
        int wi = w;
#pragma unroll
        for (int d = 1; d < 32; d <<= 1) {
            int v = __shfl_up_sync(0xFFFFFFFFu, wi, d);
            if (lane >= d) wi += v;
        }
        wsum[lane] = wi - w;            // exclusive warp base
    }
    __syncthreads();
    int excl = wsum[warp] + inc - tot;
#pragma unroll
    for (int j = 0; j < CH; j++) {
        int i = base + j;
        if (i < N_NODES) {
            int o = excl + loc[j];
            g_csr_off[i] = o;
            g_cursor[i] = o;
            g_srcnorm[i] = rsqrtf(fmaxf(g_outdeg[i], 1.0f));
            g_dstnorm[i] = rsqrtf(fmaxf((float)g_indeg_i[i], 1.0f));
        }
    }
    if (t == 1023) g_csr_off[N_NODES] = wsum[31] + inc; // total (warp31 base + its inc)
}

__global__ void csr_fill_kernel(const void* src, const void* dst, int E) {
    int i = blockIdx.x * blockDim.x + threadIdx.x;
    if (i >= E) return;
    int is64 = g_is64;
    int s = loadIdx(src, i, is64);
    int d = loadIdx(dst, i, is64);
    int p = atomicAdd(&g_cursor[d], 1);
    g_esrc[p] = s;
    atomicAdd(&g_s0[d], g_srcnorm[s]);
}

__global__ void stats_kernel(const float* __restrict__ x) {
    int col = threadIdx.x;                 // 512
    float s = 0.f, ss = 0.f;
    for (int row = blockIdx.x; row < N_NODES; row += gridDim.x) {
        float v = x[row * D + col];
        s += v;
        ss += v * v;
    }
    atomicAdd(&g_sum[col], s);
    atomicAdd(&g_sumsq[col], ss);
}

// gather + fused BN + dst-norm + bf16 hi/lo split -> interleaved A'
// agg = (inv*gamma*(V - mu*s0) + beta*s0) * dn, V = sum x[src]*srcnorm[src]
__global__ __launch_bounds__(256)
void gather_kernel(const float* __restrict__ x,
                   const float* __restrict__ gamma,
                   const float* __restrict__ beta) {
    int gw = (blockIdx.x * 256 + threadIdx.x) >> 5;
    if (gw >= N_NODES) return;
    int lane = threadIdx.x & 31;
    int beg = g_csr_off[gw];
    int end = g_csr_off[gw + 1];
    float4 a0 = make_float4(0, 0, 0, 0), a1 = a0, a2 = a0, a3 = a0;
    int e = beg;
    for (; e + 1 < end; e += 2) {
        int s0i = g_esrc[e];
        int s1i = g_esrc[e + 1];
        float n0 = g_srcnorm[s0i];
        float n1 = g_srcnorm[s1i];
        const float4* r0 = (const float4*)&x[(long)s0i * D];
        const float4* r1 = (const float4*)&x[(long)s1i * D];
        float4 v0 = r0[lane], v1 = r0[lane + 32], v2 = r0[lane + 64], v3 = r0[lane + 96];
        float4 w0 = r1[lane], w1 = r1[lane + 32], w2 = r1[lane + 64], w3 = r1[lane + 96];
        a0.x += n0 * v0.x + n1 * w0.x; a0.y += n0 * v0.y + n1 * w0.y;
        a0.z += n0 * v0.z + n1 * w0.z; a0.w += n0 * v0.w + n1 * w0.w;
        a1.x += n0 * v1.x + n1 * w1.x; a1.y += n0 * v1.y + n1 * w1.y;
        a1.z += n0 * v1.z + n1 * w1.z; a1.w += n0 * v1.w + n1 * w1.w;
        a2.x += n0 * v2.x + n1 * w2.x; a2.y += n0 * v2.y + n1 * w2.y;
        a2.z += n0 * v2.z + n1 * w2.z; a2.w += n0 * v2.w + n1 * w2.w;
        a3.x += n0 * v3.x + n1 * w3.x; a3.y += n0 * v3.y + n1 * w3.y;
        a3.z += n0 * v3.z + n1 * w3.z; a3.w += n0 * v3.w + n1 * w3.w;
    }
    if (e < end) {
        int s0i = g_esrc[e];
        float n0 = g_srcnorm[s0i];
        const float4* r0 = (const float4*)&x[(long)s0i * D];
        float4 v0 = r0[lane], v1 = r0[lane + 32], v2 = r0[lane + 64], v3 = r0[lane + 96];
        a0.x += n0 * v0.x; a0.y += n0 * v0.y; a0.z += n0 * v0.z; a0.w += n0 * v0.w;
        a1.x += n0 * v1.x; a1.y += n0 * v1.y; a1.z += n0 * v1.z; a1.w += n0 * v1.w;
        a2.x += n0 * v2.x; a2.y += n0 * v2.y; a2.z += n0 * v2.z; a2.w += n0 * v2.w;
        a3.x += n0 * v3.x; a3.y += n0 * v3.y; a3.z += n0 * v3.z; a3.w += n0 * v3.w;
    }
    float s0 = g_s0[gw];
    float dn = g_dstnorm[gw];
    const float invN = 1.0f / (float)N_NODES;
    float4 av[4] = {a0, a1, a2, a3};
    long rbase = (long)gw * KP;
#pragma unroll
    for (int i = 0; i < 4; i++) {
        int c = i * 128 + lane * 4;
        float4 sm4 = *(const float4*)&g_sum[c];
        float4 sq4 = *(const float4*)&g_sumsq[c];
        float4 gm4 = *(const float4*)&gamma[c];
        float4 bt4 = *(const float4*)&beta[c];
        float V[4] = {av[i].x, av[i].y, av[i].z, av[i].w};
        float smv[4] = {sm4.x, sm4.y, sm4.z, sm4.w};
        float sqv[4] = {sq4.x, sq4.y, sq4.z, sq4.w};
        float gmv[4] = {gm4.x, gm4.y, gm4.z, gm4.w};
        float btv[4] = {bt4.x, bt4.y, bt4.z, bt4.w};
        bf16 hi[4], lo[4];
#pragma unroll
        for (int q = 0; q < 4; q++) {
            float mu = smv[q] * invN;
            float var = sqv[q] * invN - mu * mu;
            float sc = rsqrtf(var + EPS) * gmv[q];
            float val = (sc * (V[q] - mu * s0) + btv[q] * s0) * dn;
            hi[q] = __float2bfloat16(val);
            lo[q] = __float2bfloat16(val - __bfloat162float(hi[q]));
        }
        long k = i * 128 + lane * 4;
        *(uint2*)&g_Aint[rbase + k] = *(uint2*)hi;
        *(uint2*)&g_Aint[rbase + 512 + k] = *(uint2*)hi;
        *(uint2*)&g_Aint[rbase + 1024 + k] = *(uint2*)lo;
    }
}

// W transpose + bf16 hi/lo split into interleaved W' = [Whi | Wlo | Whi]
__global__ void wconv_kernel(const float* __restrict__ W) {
    __shared__ float tile[32][33];
    int l = blockIdx.z;
    int k = blockIdx.y * 32 + threadIdx.y;
    int n = blockIdx.x * 32 + threadIdx.x;
    tile[threadIdx.y][threadIdx.x] = W[(long)l * D * D + k * D + n];
    __syncthreads();
    int on = blockIdx.x * 32 + threadIdx.y;
    int ok = blockIdx.y * 32 + threadIdx.x;
    float v = tile[threadIdx.x][threadIdx.y];
    bf16 hi = __float2bfloat16(v);
    bf16 lo = __float2bfloat16(v - __bfloat162float(hi));
    long rbase = (long)l * D * KP + (long)on * KP;
    g_Wint[rbase + ok] = hi;
    g_Wint[rbase + 512 + ok] = lo;
    g_Wint[rbase + 1024 + ok] = hi;
}

// ---------------- mma.sync bf16 GEMM: out = relu(A' @ W'^T + b) ----------------
// K'=1536, block 128x128, BK=64, 3-stage cp.async, 8 warps (32x64), ldmatrix.x4
#define BK 64
#define SROW 72                          /* 64 + 8 pad halves; 144B row stride */
#define MAT_BYTES (128 * SROW * 2)       /* 18432 */
#define STAGE_BYTES (2 * MAT_BYTES)      /* 36864 */
#define NSTAGE 3
#define GSMEM_TOT (NSTAGE * STAGE_BYTES) /* 110592 */
#define NKC (KP / BK)                    /* 24 */

__global__ __launch_bounds__(256)
void mma_gemm_kernel(const bf16* __restrict__ Wp,    // [n][KP]
                     const float* __restrict__ bias,
                     float* __restrict__ out) {
    extern __shared__ bf16 sm[];
    uint32_t sbase = smem_u32(sm);
    int tid = threadIdx.x;
    int m0 = blockIdx.y * 128;
    int n0 = blockIdx.x * 128;

    int lane = tid & 31;
    int warp = tid >> 5;
    int wm = warp >> 1;                 // 0..3 (rows, 32 each)
    int wn = warp & 1;                  // 0..1 (cols, 64 each)
    int lq = lane >> 2;                 // 0..7
    int lr = (lane & 3) * 2;            // 0,2,4,6

    int lrow = lane & 15;
    int lcol8 = (lane >> 4) << 3;
    uint32_t a_lane_off = (uint32_t)(((wm * 32 + lrow) * SROW + lcol8) * 2);
    uint32_t b_lane_off = (uint32_t)(((wn * 64 + lrow) * SROW + lcol8) * 2);

    // global load: thread -> (row = tid>>1, 4 consecutive 16B segs)
    int ldr = tid >> 1;                 // 0..127
    int seg0 = (tid & 1) * 4;           // 0 or 4

    const bf16* gA = &g_Aint[(long)(m0 + ldr) * KP];
    const bf16* gB = &Wp[(long)(n0 + ldr) * KP];
    uint32_t srow_off = (uint32_t)(ldr * SROW * 2 + seg0 * 16);

    float acc[2][8][4];
#pragma unroll
    for (int mt = 0; mt < 2; mt++)
#pragma unroll
        for (int nt = 0; nt < 8; nt++)
#pragma unroll
            for (int q = 0; q < 4; q++) acc[mt][nt][q] = 0.f;

#define ISSUE_CHUNK(kc, st) do {                                                      \
    uint32_t _b = sbase + (uint32_t)(st) * STAGE_BYTES + srow_off;                    \
    const char* _ga = (const char*)(gA + (kc) * BK) + seg0 * 16;                      \
    const char* _gb = (const char*)(gB + (kc) * BK) + seg0 * 16;                      \
    CP16(_b,      _ga);      CP16(_b + 16,      _ga + 16);                            \
    CP16(_b + 32, _ga + 32); CP16(_b + 48,      _ga + 48);                            \
    CP16(_b + MAT_BYTES,      _gb);      CP16(_b + MAT_BYTES + 16, _gb + 16);         \
    CP16(_b + MAT_BYTES + 32, _gb + 32); CP16(_b + MAT_BYTES + 48, _gb + 48);         \
    CP_COMMIT();                                                                      \
} while (0)

    ISSUE_CHUNK(0, 0);
    ISSUE_CHUNK(1, 1);

    int st = 0;
    for (int kc = 0; kc < NKC; kc++) {
        if (kc + 2 < NKC) {
            int ns = st + 2; if (ns >= NSTAGE) ns -= NSTAGE;
            ISSUE_CHUNK(kc + 2, ns);
        }
        CP_WAIT2();
        __syncthreads();

        uint32_t sa = sbase + st * STAGE_BYTES + a_lane_off;
        uint32_t sb = sbase + st * STAGE_BYTES + MAT_BYTES + b_lane_off;

#pragma unroll
        for (int ks = 0; ks < 4; ks++) {
            uint32_t koff = (uint32_t)(ks * 32);     // 16 halves = 32 B
            uint32_t af[2][4], bfr[8][2];
#pragma unroll
            for (int mt = 0; mt < 2; mt++) {
                uint32_t toff = (uint32_t)(mt * 16 * SROW * 2) + koff;
                LDSM4(af[mt][0], af[mt][1], af[mt][2], af[mt][3], sa + toff);
            }
#pragma unroll
            for (int p = 0; p < 4; p++) {
                uint32_t toff = (uint32_t)(p * 16 * SROW * 2) + koff;
                LDSM4(bfr[2 * p][0], bfr[2 * p + 1][0], bfr[2 * p][1], bfr[2 * p + 1][1],
                      sb + toff);
            }
#pragma unroll
            for (int mt = 0; mt < 2; mt++)
#pragma unroll
                for (int nt = 0; nt < 8; nt++)
                    MMA_BF16(acc[mt][nt], af[mt], bfr[nt]);
        }
        __syncthreads();
        st++; if (st >= NSTAGE) st = 0;
    }

    // epilogue
#pragma unroll
    for (int mt = 0; mt < 2; mt++) {
        int gr0 = m0 + wm * 32 + mt * 16 + lq;
        int gr1 = gr0 + 8;
#pragma unroll
        for (int nt = 0; nt < 8; nt++) {
            int gc = n0 + wn * 64 + nt * 8 + lr;
            float2 bv = *(const float2*)&bias[gc];
            if (gr0 < N_NODES) {
                float2 o0;
                o0.x = fmaxf(acc[mt][nt][0] + bv.x, 0.f);
                o0.y = fmaxf(acc[mt][nt][1] + bv.y, 0.f);
                *(float2*)&out[(long)gr0 * D + gc] = o0;
            }
            if (gr1 < N_NODES) {
                float2 o1;
                o1.x = fmaxf(acc[mt][nt][2] + bv.x, 0.f);
                o1.y = fmaxf(acc[mt][nt][3] + bv.y, 0.f);
                *(float2*)&out[(long)gr1 * D + gc] = o1;
            }
        }
    }
}

// ---------------- launch ----------------
extern "C" void kernel_launch(void* const* d_in, const int* in_sizes, int n_in,
                              void* d_out, int out_size) {
    const float* x_in  = (const float*)d_in[0];
    const void*  src   = d_in[1];
    const void*  dst   = d_in[2];
    const float* gamma = (const float*)d_in[3];
    const float* beta  = (const float*)d_in[4];
    const float* W     = (const float*)d_in[5];
    const float* bias  = (const float*)d_in[6];
    float* out = (float*)d_out;
    int E = in_sizes[1];

    float *p_xa, *p_xb;
    bf16 *p_Wint;
    cudaGetSymbolAddress((void**)&p_xa, g_xa);
    cudaGetSymbolAddress((void**)&p_xb, g_xb);
    cudaGetSymbolAddress((void**)&p_Wint, g_Wint);

    cudaFuncSetAttribute(mma_gemm_kernel,
                         cudaFuncAttributeMaxDynamicSharedMemorySize, GSMEM_TOT);

    dim3 ggrid(D / 128, N_PAD / 128);

    // setup — index 3 (profiled slot) = stats_kernel layer 0
    zero_setup_kernel<<<(N_NODES + 255) / 256, 256>>>();                 // 0
    zero_sums_kernel<<<1, 512>>>();                                      // 1
    detect_idx_kernel<<<1, 256>>>(src);                                  // 2
    stats_kernel<<<128, 512>>>(x_in);                                    // 3 (profiled)
    degree_kernel<<<(E + 255) / 256, 256>>>(src, dst, E);                // 4
    scan_kernel<<<1, 1024>>>();                                          // 5
    csr_fill_kernel<<<(E + 255) / 256, 256>>>(src, dst, E);              // 6
    {
        dim3 wg(D / 32, D / 32, NLAYERS);
        dim3 wb(32, 32);
        wconv_kernel<<<wg, wb>>>(W);                                     // 7
    }

    const float* cur = x_in;
    for (int l = 0; l < NLAYERS; l++) {
        float* nxt = (l == NLAYERS - 1) ? out : ((l & 1) ? p_xb : p_xa);
        if (l > 0) {
            zero_sums_kernel<<<1, 512>>>();
            stats_kernel<<<128, 512>>>(cur);
        }
        gather_kernel<<<(N_NODES * 32 + 255) / 256, 256>>>(cur, gamma + l * D, beta + l * D);
        mma_gemm_kernel<<<ggrid, 256, GSMEM_TOT>>>(
            p_Wint + (long)l * D * KP, bias + l * D, nxt);
        cur = nxt;
    }
}

// round 10
// speedup vs baseline: 1.1330x; 1.1330x over previous
#include <cuda_runtime.h>
#include <cuda_bf16.h>
#include <cstdint>

#define N_NODES 10000
#define N_PAD   10112   /* 79 * 128 */
#define D 512
#define KP 1536         /* interleaved K' = 3*D */
#define EPS 1e-5f
#define NLAYERS 3
#define E_MAX 262144

typedef __nv_bfloat16 bf16;

// ---------------- scratch (static device globals; no allocs) ----------------
__device__ float g_xa[N_NODES * D];    // layer ping
__device__ float g_xb[N_NODES * D];    // layer pong
__device__ bf16  g_Aint[N_PAD * KP];   // [Ahi | Ahi | Alo] (pad rows stay 0)
__device__ bf16  g_Wint[NLAYERS * D * KP];  // W^T' = [Whi | Wlo | Whi]
__device__ float g_outdeg[N_NODES];
__device__ int   g_indeg_i[N_NODES];
__device__ float g_srcnorm[N_NODES];
__device__ float g_dstnorm[N_NODES];
__device__ float g_s0[N_NODES];        // sum of srcnorm over in-neighbors
__device__ float g_sum[D];
__device__ float g_sumsq[D];
__device__ int   g_csr_off[N_NODES + 1];
__device__ int   g_cursor[N_NODES];
__device__ int   g_esrc[E_MAX];
__device__ int   g_is64;

// ---------------- PTX helpers ----------------
__device__ __forceinline__ uint32_t smem_u32(const void* p) {
    uint32_t a;
    asm("{ .reg .u64 t; cvta.to.shared.u64 t, %1; cvt.u32.u64 %0, t; }" : "=r"(a) : "l"(p));
    return a;
}
#define CP16(s, g) asm volatile("cp.async.cg.shared.global [%0], [%1], 16;" :: "r"(s), "l"(g) : "memory")
#define CP_COMMIT() asm volatile("cp.async.commit_group;" ::: "memory")
#define CP_WAIT2()  asm volatile("cp.async.wait_group 2;" ::: "memory")
#define MMA_BF16(acc, a, b)                                                           \
    asm volatile("mma.sync.aligned.m16n8k16.row.col.f32.bf16.bf16.f32 "               \
        "{%0,%1,%2,%3},{%4,%5,%6,%7},{%8,%9},{%0,%1,%2,%3};"                          \
        : "+f"((acc)[0]), "+f"((acc)[1]), "+f"((acc)[2]), "+f"((acc)[3])              \
        : "r"((a)[0]), "r"((a)[1]), "r"((a)[2]), "r"((a)[3]),                         \
          "r"((b)[0]), "r"((b)[1]))
#define LDSM4(r0, r1, r2, r3, addr)                                                   \
    asm volatile("ldmatrix.sync.aligned.m8n8.x4.shared.b16 {%0,%1,%2,%3}, [%4];"      \
        : "=r"(r0), "=r"(r1), "=r"(r2), "=r"(r3) : "r"(addr))

// ---------------- helpers ----------------
__device__ __forceinline__ int loadIdx(const void* p, int i, int is64) {
    if (is64) return (int)((const long long*)p)[i];
    return ((const int*)p)[i];
}

// ---------------- small kernels ----------------
__global__ void zero_setup_kernel() {
    int i = blockIdx.x * blockDim.x + threadIdx.x;
    if (i < N_NODES) {
        g_outdeg[i] = 0.0f;
        g_indeg_i[i] = 0;
        g_s0[i] = 0.0f;
    }
}
__global__ void zero_sums_kernel() {
    int i = threadIdx.x;        // 512
    g_sum[i] = 0.0f;
    g_sumsq[i] = 0.0f;
}

__global__ void detect_idx_kernel(const void* src) {
    __shared__ int cnt;
    if (threadIdx.x == 0) cnt = 0;
    __syncthreads();
    const int* p = (const int*)src;
    int v = p[2 * threadIdx.x + 1];
    if (v != 0) atomicAdd(&cnt, 1);
    __syncthreads();
    if (threadIdx.x == 0) g_is64 = (cnt == 0) ? 1 : 0;
}

__global__ void degree_kernel(const void* src, const void* dst, int E) {
    int i = blockIdx.x * blockDim.x + threadIdx.x;
    if (i >= E) return;
    int is64 = g_is64;
    int s = loadIdx(src, i, is64);
    int d = loadIdx(dst, i, is64);
    atomicAdd(&g_outdeg[s], 1.0f);
    atomicAdd(&g_indeg_i[d], 1);
}

// single-block scan via warp shuffles (2 barriers) + norms
__global__ void scan_kernel() {
    __shared__ int wsum[32];
    const int CH = 10;
    int t = threadIdx.x;
    int lane = t & 31, warp = t >> 5;
    int base = t * CH;
    int loc[CH];
    int tot = 0;
#pragma unroll
    for (int j = 0; j < CH; j++) {
        int i = base + j;
        int d = (i < N_NODES) ? g_indeg_i[i] : 0;
        loc[j] = tot;
        tot += d;
    }
    int inc = tot;
#pragma unroll
    for (int d = 1; d < 32; d <<= 1) {
        int v = __shfl_up_sync(0xFFFFFFFFu, inc, d);
        if (lane >= d) inc += v;
    }
    if (lane == 31) wsum[warp] = inc;
    __syncthreads();
    if (warp == 0) {
        int w = wsum[lane];
        int wi = w;
#pragma unroll
        for (int d = 1; d < 32; d <<= 1) {
            int v = __shfl_up_sync(0xFFFFFFFFu, wi, d);
            if (lane >= d) wi += v;
        }
        wsum[lane] = wi - w;            // exclusive warp base
    }
    __syncthreads();
    int excl = wsum[warp] + inc - tot;
#pragma unroll
    for (int j = 0; j < CH; j++) {
        int i = base + j;
        if (i < N_NODES) {
            int o = excl + loc[j];
            g_csr_off[i] = o;
            g_cursor[i] = o;
            g_srcnorm[i] = rsqrtf(fmaxf(g_outdeg[i], 1.0f));
            g_dstnorm[i] = rsqrtf(fmaxf((float)g_indeg_i[i], 1.0f));
        }
    }
    if (t == 1023) g_csr_off[N_NODES] = wsum[31] + inc;
}

__global__ void csr_fill_kernel(const void* src, const void* dst, int E) {
    int i = blockIdx.x * blockDim.x + threadIdx.x;
    if (i >= E) return;
    int is64 = g_is64;
    int s = loadIdx(src, i, is64);
    int d = loadIdx(dst, i, is64);
    int p = atomicAdd(&g_cursor[d], 1);
    g_esrc[p] = s;
    atomicAdd(&g_s0[d], g_srcnorm[s]);
}

// column sums: 256 blocks x 128 threads; thread = one float4 column slice
#define STATS_BLOCKS 256
__global__ __launch_bounds__(128)
void stats_kernel(const float* __restrict__ x) {
    int c4 = threadIdx.x;                  // 0..127 float4 column
    float4 s = make_float4(0, 0, 0, 0);
    float4 q = make_float4(0, 0, 0, 0);
    const float4* xr = (const float4*)x;
#pragma unroll 4
    for (int row = blockIdx.x; row < N_NODES; row += STATS_BLOCKS) {
        float4 v = xr[(long)row * 128 + c4];
        s.x += v.x; s.y += v.y; s.z += v.z; s.w += v.w;
        q.x += v.x * v.x; q.y += v.y * v.y; q.z += v.z * v.z; q.w += v.w * v.w;
    }
    int c = c4 * 4;
    atomicAdd(&g_sum[c + 0], s.x); atomicAdd(&g_sum[c + 1], s.y);
    atomicAdd(&g_sum[c + 2], s.z); atomicAdd(&g_sum[c + 3], s.w);
    atomicAdd(&g_sumsq[c + 0], q.x); atomicAdd(&g_sumsq[c + 1], q.y);
    atomicAdd(&g_sumsq[c + 2], q.z); atomicAdd(&g_sumsq[c + 3], q.w);
}

// gather + fused BN + dst-norm + bf16 hi/lo split -> interleaved A'
__global__ __launch_bounds__(256)
void gather_kernel(const float* __restrict__ x,
                   const float* __restrict__ gamma,
                   const float* __restrict__ beta) {
    int gw = (blockIdx.x * 256 + threadIdx.x) >> 5;
    if (gw >= N_NODES) return;
    int lane = threadIdx.x & 31;
    int beg = g_csr_off[gw];
    int end = g_csr_off[gw + 1];
    float4 a0 = make_float4(0, 0, 0, 0), a1 = a0, a2 = a0, a3 = a0;
    int e = beg;
    for (; e + 1 < end; e += 2) {
        int s0i = g_esrc[e];
        int s1i = g_esrc[e + 1];
        float n0 = g_srcnorm[s0i];
        float n1 = g_srcnorm[s1i];
        const float4* r0 = (const float4*)&x[(long)s0i * D];
        const float4* r1 = (const float4*)&x[(long)s1i * D];
        float4 v0 = r0[lane], v1 = r0[lane + 32], v2 = r0[lane + 64], v3 = r0[lane + 96];
        float4 w0 = r1[lane], w1 = r1[lane + 32], w2 = r1[lane + 64], w3 = r1[lane + 96];
        a0.x += n0 * v0.x + n1 * w0.x; a0.y += n0 * v0.y + n1 * w0.y;
        a0.z += n0 * v0.z + n1 * w0.z; a0.w += n0 * v0.w + n1 * w0.w;
        a1.x += n0 * v1.x + n1 * w1.x; a1.y += n0 * v1.y + n1 * w1.y;
        a1.z += n0 * v1.z + n1 * w1.z; a1.w += n0 * v1.w + n1 * w1.w;
        a2.x += n0 * v2.x + n1 * w2.x; a2.y += n0 * v2.y + n1 * w2.y;
        a2.z += n0 * v2.z + n1 * w2.z; a2.w += n0 * v2.w + n1 * w2.w;
        a3.x += n0 * v3.x + n1 * w3.x; a3.y += n0 * v3.y + n1 * w3.y;
        a3.z += n0 * v3.z + n1 * w3.z; a3.w += n0 * v3.w + n1 * w3.w;
    }
    if (e < end) {
        int s0i = g_esrc[e];
        float n0 = g_srcnorm[s0i];
        const float4* r0 = (const float4*)&x[(long)s0i * D];
        float4 v0 = r0[lane], v1 = r0[lane + 32], v2 = r0[lane + 64], v3 = r0[lane + 96];
        a0.x += n0 * v0.x; a0.y += n0 * v0.y; a0.z += n0 * v0.z; a0.w += n0 * v0.w;
        a1.x += n0 * v1.x; a1.y += n0 * v1.y; a1.z += n0 * v1.z; a1.w += n0 * v1.w;
        a2.x += n0 * v2.x; a2.y += n0 * v2.y; a2.z += n0 * v2.z; a2.w += n0 * v2.w;
        a3.x += n0 * v3.x; a3.y += n0 * v3.y; a3.z += n0 * v3.z; a3.w += n0 * v3.w;
    }
    float s0 = g_s0[gw];
    float dn = g_dstnorm[gw];
    const float invN = 1.0f / (float)N_NODES;
    float4 av[4] = {a0, a1, a2, a3};
    long rbase = (long)gw * KP;
#pragma unroll
    for (int i = 0; i < 4; i++) {
        int c = i * 128 + lane * 4;
        float4 sm4 = *(const float4*)&g_sum[c];
        float4 sq4 = *(const float4*)&g_sumsq[c];
        float4 gm4 = *(const float4*)&gamma[c];
        float4 bt4 = *(const float4*)&beta[c];
        float V[4] = {av[i].x, av[i].y, av[i].z, av[i].w};
        float smv[4] = {sm4.x, sm4.y, sm4.z, sm4.w};
        float sqv[4] = {sq4.x, sq4.y, sq4.z, sq4.w};
        float gmv[4] = {gm4.x, gm4.y, gm4.z, gm4.w};
        float btv[4] = {bt4.x, bt4.y, bt4.z, bt4.w};
        bf16 hi[4], lo[4];
#pragma unroll
        for (int q = 0; q < 4; q++) {
            float mu = smv[q] * invN;
            float var = sqv[q] * invN - mu * mu;
            float sc = rsqrtf(var + EPS) * gmv[q];
            float val = (sc * (V[q] - mu * s0) + btv[q] * s0) * dn;
            hi[q] = __float2bfloat16(val);
            lo[q] = __float2bfloat16(val - __bfloat162float(hi[q]));
        }
        long k = i * 128 + lane * 4;
        *(uint2*)&g_Aint[rbase + k] = *(uint2*)hi;
        *(uint2*)&g_Aint[rbase + 512 + k] = *(uint2*)hi;
        *(uint2*)&g_Aint[rbase + 1024 + k] = *(uint2*)lo;
    }
}

// W transpose + bf16 hi/lo split into interleaved W' = [Whi | Wlo | Whi]
__global__ void wconv_kernel(const float* __restrict__ W) {
    __shared__ float tile[32][33];
    int l = blockIdx.z;
    int k = blockIdx.y * 32 + threadIdx.y;
    int n = blockIdx.x * 32 + threadIdx.x;
    tile[threadIdx.y][threadIdx.x] = W[(long)l * D * D + k * D + n];
    __syncthreads();
    int on = blockIdx.x * 32 + threadIdx.y;
    int ok = blockIdx.y * 32 + threadIdx.x;
    float v = tile[threadIdx.x][threadIdx.y];
    bf16 hi = __float2bfloat16(v);
    bf16 lo = __float2bfloat16(v - __bfloat162float(hi));
    long rbase = (long)l * D * KP + (long)on * KP;
    g_Wint[rbase + ok] = hi;
    g_Wint[rbase + 512 + ok] = lo;
    g_Wint[rbase + 1024 + ok] = hi;
}

// ---------------- mma.sync bf16 GEMM (R7 config: BK=32, 4-stage) ----------------
#define SROW 40                          /* smem row stride in halves (80B) */
#define MAT_BYTES (128 * SROW * 2)       /* 10240 */
#define STAGE_BYTES (2 * MAT_BYTES)      /* 20480 */
#define NSTAGE 4
#define GSMEM_TOT (NSTAGE * STAGE_BYTES) /* 81920 */
#define NKC (KP / 32)                    /* 48 */

__global__ __launch_bounds__(256)
void mma_gemm_kernel(const bf16* __restrict__ Wp,    // [n][KP]
                     const float* __restrict__ bias,
                     float* __restrict__ out) {
    extern __shared__ bf16 sm[];
    uint32_t sbase = smem_u32(sm);
    int tid = threadIdx.x;
    int m0 = blockIdx.y * 128;
    int n0 = blockIdx.x * 128;

    int lane = tid & 31;
    int warp = tid >> 5;
    int wm = warp >> 1;                 // 0..3 (rows, 32 each)
    int wn = warp & 1;                  // 0..1 (cols, 64 each)
    int lq = lane >> 2;                 // 0..7
    int lr = (lane & 3) * 2;            // 0,2,4,6

    int lrow = lane & 15;
    int lcol8 = (lane >> 4) << 3;
    uint32_t a_lane_off = (uint32_t)(((wm * 32 + lrow) * SROW + lcol8) * 2);
    uint32_t b_lane_off = (uint32_t)(((wn * 64 + lrow) * SROW + lcol8) * 2);

    int ldr = tid >> 1;                 // 0..127
    int seg0 = (tid & 1) * 2;           // 0 or 2

    const bf16* gA = &g_Aint[(long)(m0 + ldr) * KP];
    const bf16* gB = &Wp[(long)(n0 + ldr) * KP];
    uint32_t srow_off = (uint32_t)(ldr * SROW * 2 + seg0 * 16);

    float acc[2][8][4];
#pragma unroll
    for (int mt = 0; mt < 2; mt++)
#pragma unroll
        for (int nt = 0; nt < 8; nt++)
#pragma unroll
            for (int q = 0; q < 4; q++) acc[mt][nt][q] = 0.f;

#define ISSUE_CHUNK(kc, st) do {                                                      \
    uint32_t _b = sbase + (uint32_t)(st) * STAGE_BYTES + srow_off;                    \
    const char* _ga = (const char*)(gA + (kc) * 32) + seg0 * 16;                      \
    const char* _gb = (const char*)(gB + (kc) * 32) + seg0 * 16;                      \
    CP16(_b, _ga); CP16(_b + 16, _ga + 16);                                           \
    CP16(_b + MAT_BYTES, _gb); CP16(_b + MAT_BYTES + 16, _gb + 16);                   \
    CP_COMMIT();                                                                      \
} while (0)

    ISSUE_CHUNK(0, 0);
    ISSUE_CHUNK(1, 1);
    ISSUE_CHUNK(2, 2);

    for (int kc = 0; kc < NKC; kc++) {
        CP_WAIT2();
        __syncthreads();
        if (kc + 3 < NKC) ISSUE_CHUNK(kc + 3, (kc + 3) & 3);

        int st = kc & 3;
        uint32_t sa = sbase + st * STAGE_BYTES + a_lane_off;
        uint32_t sb = sbase + st * STAGE_BYTES + MAT_BYTES + b_lane_off;

#pragma unroll
        for (int ks = 0; ks < 2; ks++) {
            uint32_t koff = (uint32_t)(ks * 32);
            uint32_t af[2][4], bfr[8][2];
#pragma unroll
            for (int mt = 0; mt < 2; mt++) {
                uint32_t toff = (uint32_t)(mt * 16 * SROW * 2) + koff;
                LDSM4(af[mt][0], af[mt][1], af[mt][2], af[mt][3], sa + toff);
            }
#pragma unroll
            for (int p = 0; p < 4; p++) {
                uint32_t toff = (uint32_t)(p * 16 * SROW * 2) + koff;
                LDSM4(bfr[2 * p][0], bfr[2 * p + 1][0], bfr[2 * p][1], bfr[2 * p + 1][1],
                      sb + toff);
            }
#pragma unroll
            for (int mt = 0; mt < 2; mt++)
#pragma unroll
                for (int nt = 0; nt < 8; nt++)
                    MMA_BF16(acc[mt][nt], af[mt], bfr[nt]);
        }
    }

    // epilogue
#pragma unroll
    for (int mt = 0; mt < 2; mt++) {
        int gr0 = m0 + wm * 32 + mt * 16 + lq;
        int gr1 = gr0 + 8;
#pragma unroll
        for (int nt = 0; nt < 8; nt++) {
            int gc = n0 + wn * 64 + nt * 8 + lr;
            float2 bv = *(const float2*)&bias[gc];
            if (gr0 < N_NODES) {
                float2 o0;
                o0.x = fmaxf(acc[mt][nt][0] + bv.x, 0.f);
                o0.y = fmaxf(acc[mt][nt][1] + bv.y, 0.f);
                *(float2*)&out[(long)gr0 * D + gc] = o0;
            }
            if (gr1 < N_NODES) {
                float2 o1;
                o1.x = fmaxf(acc[mt][nt][2] + bv.x, 0.f);
                o1.y = fmaxf(acc[mt][nt][3] + bv.y, 0.f);
                *(float2*)&out[(long)gr1 * D + gc] = o1;
            }
        }
    }
}

// ---------------- launch ----------------
extern "C" void kernel_launch(void* const* d_in, const int* in_sizes, int n_in,
                              void* d_out, int out_size) {
    const float* x_in  = (const float*)d_in[0];
    const void*  src   = d_in[1];
    const void*  dst   = d_in[2];
    const float* gamma = (const float*)d_in[3];
    const float* beta  = (const float*)d_in[4];
    const float* W     = (const float*)d_in[5];
    const float* bias  = (const float*)d_in[6];
    float* out = (float*)d_out;
    int E = in_sizes[1];

    float *p_xa, *p_xb;
    bf16 *p_Wint;
    cudaGetSymbolAddress((void**)&p_xa, g_xa);
    cudaGetSymbolAddress((void**)&p_xb, g_xb);
    cudaGetSymbolAddress((void**)&p_Wint, g_Wint);

    cudaFuncSetAttribute(mma_gemm_kernel,
                         cudaFuncAttributeMaxDynamicSharedMemorySize, GSMEM_TOT);

    dim3 ggrid(D / 128, N_PAD / 128);

    // setup — index 3 (profiled slot) = new stats_kernel
    zero_setup_kernel<<<(N_NODES + 255) / 256, 256>>>();                 // 0
    zero_sums_kernel<<<1, 512>>>();                                      // 1
    detect_idx_kernel<<<1, 256>>>(src);                                  // 2
    stats_kernel<<<STATS_BLOCKS, 128>>>(x_in);                           // 3 (profiled)
    degree_kernel<<<(E + 255) / 256, 256>>>(src, dst, E);                // 4
    scan_kernel<<<1, 1024>>>();                                          // 5
    csr_fill_kernel<<<(E + 255) / 256, 256>>>(src, dst, E);              // 6
    {
        dim3 wg(D / 32, D / 32, NLAYERS);
        dim3 wb(32, 32);
        wconv_kernel<<<wg, wb>>>(W);                                     // 7
    }

    const float* cur = x_in;
    for (int l = 0; l < NLAYERS; l++) {
        float* nxt = (l == NLAYERS - 1) ? out : ((l & 1) ? p_xb : p_xa);
        if (l > 0) {
            zero_sums_kernel<<<1, 512>>>();
            stats_kernel<<<STATS_BLOCKS, 128>>>(cur);
        }
        gather_kernel<<<(N_NODES * 32 + 255) / 256, 256>>>(cur, gamma + l * D, beta + l * D);
        mma_gemm_kernel<<<ggrid, 256, GSMEM_TOT>>>(
            p_Wint + (long)l * D * KP, bias + l * D, nxt);
        cur = nxt;
    }
}

// round 11
// speedup vs baseline: 1.1502x; 1.0152x over previous
#include <cuda_runtime.h>
#include <cuda_bf16.h>
#include <cstdint>

#define N_NODES 10000
#define N_PAD   10112   /* 79 * 128 */
#define D 512
#define KP 1536         /* interleaved K' = 3*D */
#define EPS 1e-5f
#define NLAYERS 3
#define E_MAX 262144

typedef __nv_bfloat16 bf16;

// ---------------- scratch (static device globals; no allocs) ----------------
__device__ float g_xa[N_NODES * D];    // layer ping
__device__ float g_xb[N_NODES * D];    // layer pong
__device__ bf16  g_Aint[N_PAD * KP];   // [Ahi | Ahi | Alo] (pad rows stay 0)
__device__ bf16  g_Wint[NLAYERS * D * KP];  // W^T' = [Whi | Wlo | Whi]
__device__ float g_outdeg[N_NODES];
__device__ int   g_indeg_i[N_NODES];
__device__ float g_srcnorm[N_NODES];
__device__ float g_dstnorm[N_NODES];
__device__ float g_s0[N_NODES];        // sum of srcnorm over in-neighbors
__device__ float g_sum[D];
__device__ float g_sumsq[D];
__device__ int   g_csr_off[N_NODES + 1];
__device__ int   g_cursor[N_NODES];
__device__ int   g_esrc[E_MAX];
__device__ int   g_is64;

// ---------------- PTX helpers ----------------
__device__ __forceinline__ uint32_t smem_u32(const void* p) {
    uint32_t a;
    asm("{ .reg .u64 t; cvta.to.shared.u64 t, %1; cvt.u32.u64 %0, t; }" : "=r"(a) : "l"(p));
    return a;
}
#define CP16(s, g) asm volatile("cp.async.cg.shared.global [%0], [%1], 16;" :: "r"(s), "l"(g) : "memory")
#define CP_COMMIT() asm volatile("cp.async.commit_group;" ::: "memory")
#define CP_WAIT2()  asm volatile("cp.async.wait_group 2;" ::: "memory")
#define MMA_BF16(acc, a, b)                                                           \
    asm volatile("mma.sync.aligned.m16n8k16.row.col.f32.bf16.bf16.f32 "               \
        "{%0,%1,%2,%3},{%4,%5,%6,%7},{%8,%9},{%0,%1,%2,%3};"                          \
        : "+f"((acc)[0]), "+f"((acc)[1]), "+f"((acc)[2]), "+f"((acc)[3])              \
        : "r"((a)[0]), "r"((a)[1]), "r"((a)[2]), "r"((a)[3]),                         \
          "r"((b)[0]), "r"((b)[1]))
#define LDSM4(r0, r1, r2, r3, addr)                                                   \
    asm volatile("ldmatrix.sync.aligned.m8n8.x4.shared.b16 {%0,%1,%2,%3}, [%4];"      \
        : "=r"(r0), "=r"(r1), "=r"(r2), "=r"(r3) : "r"(addr))

// ---------------- helpers ----------------
__device__ __forceinline__ int loadIdx(const void* p, int i, int is64) {
    if (is64) return (int)((const long long*)p)[i];
    return ((const int*)p)[i];
}

// ---------------- small kernels ----------------
__global__ void zero_setup_kernel() {
    int i = blockIdx.x * blockDim.x + threadIdx.x;
    if (i < N_NODES) {
        g_outdeg[i] = 0.0f;
        g_indeg_i[i] = 0;
        g_s0[i] = 0.0f;
    }
}
__global__ void zero_sums_kernel() {
    int i = threadIdx.x;        // 512
    g_sum[i] = 0.0f;
    g_sumsq[i] = 0.0f;
}

__global__ void detect_idx_kernel(const void* src) {
    __shared__ int cnt;
    if (threadIdx.x == 0) cnt = 0;
    __syncthreads();
    const int* p = (const int*)src;
    int v = p[2 * threadIdx.x + 1];
    if (v != 0) atomicAdd(&cnt, 1);
    __syncthreads();
    if (threadIdx.x == 0) g_is64 = (cnt == 0) ? 1 : 0;
}

__global__ void degree_kernel(const void* src, const void* dst, int E) {
    int i = blockIdx.x * blockDim.x + threadIdx.x;
    if (i >= E) return;
    int is64 = g_is64;
    int s = loadIdx(src, i, is64);
    int d = loadIdx(dst, i, is64);
    atomicAdd(&g_outdeg[s], 1.0f);
    atomicAdd(&g_indeg_i[d], 1);
}

// single-block scan via warp shuffles (2 barriers) + norms
__global__ void scan_kernel() {
    __shared__ int wsum[32];
    const int CH = 10;
    int t = threadIdx.x;
    int lane = t & 31, warp = t >> 5;
    int base = t * CH;
    int loc[CH];
    int tot = 0;
#pragma unroll
    for (int j = 0; j < CH; j++) {
        int i = base + j;
        int d = (i < N_NODES) ? g_indeg_i[i] : 0;
        loc[j] = tot;
        tot += d;
    }
    int inc = tot;
#pragma unroll
    for (int d = 1; d < 32; d <<= 1) {
        int v = __shfl_up_sync(0xFFFFFFFFu, inc, d);
        if (lane >= d) inc += v;
    }
    if (lane == 31) wsum[warp] = inc;
    __syncthreads();
    if (warp == 0) {
        int w = wsum[lane];
        int wi = w;
#pragma unroll
        for (int d = 1; d < 32; d <<= 1) {
            int v = __shfl_up_sync(0xFFFFFFFFu, wi, d);
            if (lane >= d) wi += v;
        }
        wsum[lane] = wi - w;            // exclusive warp base
    }
    __syncthreads();
    int excl = wsum[warp] + inc - tot;
#pragma unroll
    for (int j = 0; j < CH; j++) {
        int i = base + j;
        if (i < N_NODES) {
            int o = excl + loc[j];
            g_csr_off[i] = o;
            g_cursor[i] = o;
            g_srcnorm[i] = rsqrtf(fmaxf(g_outdeg[i], 1.0f));
            g_dstnorm[i] = rsqrtf(fmaxf((float)g_indeg_i[i], 1.0f));
        }
    }
    if (t == 1023) g_csr_off[N_NODES] = wsum[31] + inc;
}

__global__ void csr_fill_kernel(const void* src, const void* dst, int E) {
    int i = blockIdx.x * blockDim.x + threadIdx.x;
    if (i >= E) return;
    int is64 = g_is64;
    int s = loadIdx(src, i, is64);
    int d = loadIdx(dst, i, is64);
    int p = atomicAdd(&g_cursor[d], 1);
    g_esrc[p] = s;
    atomicAdd(&g_s0[d], g_srcnorm[s]);
}

// layer-0 column sums: 512 blocks x 256 threads (2 rows per block-step)
#define STATS_BLOCKS 512
__global__ __launch_bounds__(256)
void stats_kernel(const float* __restrict__ x) {
    int c4 = threadIdx.x & 127;            // float4 column
    int rsub = threadIdx.x >> 7;           // 0..1
    float4 s = make_float4(0, 0, 0, 0);
    float4 q = make_float4(0, 0, 0, 0);
    const float4* xr = (const float4*)x;
#pragma unroll 4
    for (int row = blockIdx.x * 2 + rsub; row < N_NODES; row += STATS_BLOCKS * 2) {
        float4 v = xr[(long)row * 128 + c4];
        s.x += v.x; s.y += v.y; s.z += v.z; s.w += v.w;
        q.x += v.x * v.x; q.y += v.y * v.y; q.z += v.z * v.z; q.w += v.w * v.w;
    }
    int c = c4 * 4;
    atomicAdd(&g_sum[c + 0], s.x); atomicAdd(&g_sum[c + 1], s.y);
    atomicAdd(&g_sum[c + 2], s.z); atomicAdd(&g_sum[c + 3], s.w);
    atomicAdd(&g_sumsq[c + 0], q.x); atomicAdd(&g_sumsq[c + 1], q.y);
    atomicAdd(&g_sumsq[c + 2], q.z); atomicAdd(&g_sumsq[c + 3], q.w);
}

// gather + fused BN + dst-norm + bf16 hi/lo split -> interleaved A'
__global__ __launch_bounds__(256)
void gather_kernel(const float* __restrict__ x,
                   const float* __restrict__ gamma,
                   const float* __restrict__ beta) {
    int gw = (blockIdx.x * 256 + threadIdx.x) >> 5;
    if (gw >= N_NODES) return;
    int lane = threadIdx.x & 31;
    int beg = g_csr_off[gw];
    int end = g_csr_off[gw + 1];
    float4 a0 = make_float4(0, 0, 0, 0), a1 = a0, a2 = a0, a3 = a0;
    int e = beg;
    for (; e + 1 < end; e += 2) {
        int s0i = g_esrc[e];
        int s1i = g_esrc[e + 1];
        float n0 = g_srcnorm[s0i];
        float n1 = g_srcnorm[s1i];
        const float4* r0 = (const float4*)&x[(long)s0i * D];
        const float4* r1 = (const float4*)&x[(long)s1i * D];
        float4 v0 = r0[lane], v1 = r0[lane + 32], v2 = r0[lane + 64], v3 = r0[lane + 96];
        float4 w0 = r1[lane], w1 = r1[lane + 32], w2 = r1[lane + 64], w3 = r1[lane + 96];
        a0.x += n0 * v0.x + n1 * w0.x; a0.y += n0 * v0.y + n1 * w0.y;
        a0.z += n0 * v0.z + n1 * w0.z; a0.w += n0 * v0.w + n1 * w0.w;
        a1.x += n0 * v1.x + n1 * w1.x; a1.y += n0 * v1.y + n1 * w1.y;
        a1.z += n0 * v1.z + n1 * w1.z; a1.w += n0 * v1.w + n1 * w1.w;
        a2.x += n0 * v2.x + n1 * w2.x; a2.y += n0 * v2.y + n1 * w2.y;
        a2.z += n0 * v2.z + n1 * w2.z; a2.w += n0 * v2.w + n1 * w2.w;
        a3.x += n0 * v3.x + n1 * w3.x; a3.y += n0 * v3.y + n1 * w3.y;
        a3.z += n0 * v3.z + n1 * w3.z; a3.w += n0 * v3.w + n1 * w3.w;
    }
    if (e < end) {
        int s0i = g_esrc[e];
        float n0 = g_srcnorm[s0i];
        const float4* r0 = (const float4*)&x[(long)s0i * D];
        float4 v0 = r0[lane], v1 = r0[lane + 32], v2 = r0[lane + 64], v3 = r0[lane + 96];
        a0.x += n0 * v0.x; a0.y += n0 * v0.y; a0.z += n0 * v0.z; a0.w += n0 * v0.w;
        a1.x += n0 * v1.x; a1.y += n0 * v1.y; a1.z += n0 * v1.z; a1.w += n0 * v1.w;
        a2.x += n0 * v2.x; a2.y += n0 * v2.y; a2.z += n0 * v2.z; a2.w += n0 * v2.w;
        a3.x += n0 * v3.x; a3.y += n0 * v3.y; a3.z += n0 * v3.z; a3.w += n0 * v3.w;
    }
    float s0 = g_s0[gw];
    float dn = g_dstnorm[gw];
    const float invN = 1.0f / (float)N_NODES;
    float4 av[4] = {a0, a1, a2, a3};
    long rbase = (long)gw * KP;
#pragma unroll
    for (int i = 0; i < 4; i++) {
        int c = i * 128 + lane * 4;
        float4 sm4 = *(const float4*)&g_sum[c];
        float4 sq4 = *(const float4*)&g_sumsq[c];
        float4 gm4 = *(const float4*)&gamma[c];
        float4 bt4 = *(const float4*)&beta[c];
        float V[4] = {av[i].x, av[i].y, av[i].z, av[i].w};
        float smv[4] = {sm4.x, sm4.y, sm4.z, sm4.w};
        float sqv[4] = {sq4.x, sq4.y, sq4.z, sq4.w};
        float gmv[4] = {gm4.x, gm4.y, gm4.z, gm4.w};
        float btv[4] = {bt4.x, bt4.y, bt4.z, bt4.w};
        bf16 hi[4], lo[4];
#pragma unroll
        for (int q = 0; q < 4; q++) {
            float mu = smv[q] * invN;
            float var = sqv[q] * invN - mu * mu;
            float sc = rsqrtf(var + EPS) * gmv[q];
            float val = (sc * (V[q] - mu * s0) + btv[q] * s0) * dn;
            hi[q] = __float2bfloat16(val);
            lo[q] = __float2bfloat16(val - __bfloat162float(hi[q]));
        }
        long k = i * 128 + lane * 4;
        *(uint2*)&g_Aint[rbase + k] = *(uint2*)hi;
        *(uint2*)&g_Aint[rbase + 512 + k] = *(uint2*)hi;
        *(uint2*)&g_Aint[rbase + 1024 + k] = *(uint2*)lo;
    }
}

// W transpose + bf16 hi/lo split into interleaved W' = [Whi | Wlo | Whi]
__global__ void wconv_kernel(const float* __restrict__ W) {
    __shared__ float tile[32][33];
    int l = blockIdx.z;
    int k = blockIdx.y * 32 + threadIdx.y;
    int n = blockIdx.x * 32 + threadIdx.x;
    tile[threadIdx.y][threadIdx.x] = W[(long)l * D * D + k * D + n];
    __syncthreads();
    int on = blockIdx.x * 32 + threadIdx.y;
    int ok = blockIdx.y * 32 + threadIdx.x;
    float v = tile[threadIdx.x][threadIdx.y];
    bf16 hi = __float2bfloat16(v);
    bf16 lo = __float2bfloat16(v - __bfloat162float(hi));
    long rbase = (long)l * D * KP + (long)on * KP;
    g_Wint[rbase + ok] = hi;
    g_Wint[rbase + 512 + ok] = lo;
    g_Wint[rbase + 1024 + ok] = hi;
}

// ---------------- mma.sync bf16 GEMM (BK=32, 4-stage) + fused next-layer stats ----
#define SROW 40                          /* smem row stride in halves (80B) */
#define MAT_BYTES (128 * SROW * 2)       /* 10240 */
#define STAGE_BYTES (2 * MAT_BYTES)      /* 20480 */
#define NSTAGE 4
#define GSMEM_TOT (NSTAGE * STAGE_BYTES) /* 81920 */
#define NKC (KP / 32)                    /* 48 */

__global__ __launch_bounds__(256)
void mma_gemm_kernel(const bf16* __restrict__ Wp,    // [n][KP]
                     const float* __restrict__ bias,
                     float* __restrict__ out,
                     int do_stats) {
    extern __shared__ bf16 sm[];
    uint32_t sbase = smem_u32(sm);
    int tid = threadIdx.x;
    int m0 = blockIdx.y * 128;
    int n0 = blockIdx.x * 128;

    int lane = tid & 31;
    int warp = tid >> 5;
    int wm = warp >> 1;                 // 0..3 (rows, 32 each)
    int wn = warp & 1;                  // 0..1 (cols, 64 each)
    int lq = lane >> 2;                 // 0..7
    int lr = (lane & 3) * 2;            // 0,2,4,6

    int lrow = lane & 15;
    int lcol8 = (lane >> 4) << 3;
    uint32_t a_lane_off = (uint32_t)(((wm * 32 + lrow) * SROW + lcol8) * 2);
    uint32_t b_lane_off = (uint32_t)(((wn * 64 + lrow) * SROW + lcol8) * 2);

    int ldr = tid >> 1;                 // 0..127
    int seg0 = (tid & 1) * 2;           // 0 or 2

    const bf16* gA = &g_Aint[(long)(m0 + ldr) * KP];
    const bf16* gB = &Wp[(long)(n0 + ldr) * KP];
    uint32_t srow_off = (uint32_t)(ldr * SROW * 2 + seg0 * 16);

    float acc[2][8][4];
#pragma unroll
    for (int mt = 0; mt < 2; mt++)
#pragma unroll
        for (int nt = 0; nt < 8; nt++)
#pragma unroll
            for (int q = 0; q < 4; q++) acc[mt][nt][q] = 0.f;

#define ISSUE_CHUNK(kc, st) do {                                                      \
    uint32_t _b = sbase + (uint32_t)(st) * STAGE_BYTES + srow_off;                    \
    const char* _ga = (const char*)(gA + (kc) * 32) + seg0 * 16;                      \
    const char* _gb = (const char*)(gB + (kc) * 32) + seg0 * 16;                      \
    CP16(_b, _ga); CP16(_b + 16, _ga + 16);                                           \
    CP16(_b + MAT_BYTES, _gb); CP16(_b + MAT_BYTES + 16, _gb + 16);                   \
    CP_COMMIT();                                                                      \
} while (0)

    ISSUE_CHUNK(0, 0);
    ISSUE_CHUNK(1, 1);
    ISSUE_CHUNK(2, 2);

    for (int kc = 0; kc < NKC; kc++) {
        CP_WAIT2();
        __syncthreads();
        if (kc + 3 < NKC) ISSUE_CHUNK(kc + 3, (kc + 3) & 3);

        int st = kc & 3;
        uint32_t sa = sbase + st * STAGE_BYTES + a_lane_off;
        uint32_t sb = sbase + st * STAGE_BYTES + MAT_BYTES + b_lane_off;

#pragma unroll
        for (int ks = 0; ks < 2; ks++) {
            uint32_t koff = (uint32_t)(ks * 32);
            uint32_t af[2][4], bfr[8][2];
#pragma unroll
            for (int mt = 0; mt < 2; mt++) {
                uint32_t toff = (uint32_t)(mt * 16 * SROW * 2) + koff;
                LDSM4(af[mt][0], af[mt][1], af[mt][2], af[mt][3], sa + toff);
            }
#pragma unroll
            for (int p = 0; p < 4; p++) {
                uint32_t toff = (uint32_t)(p * 16 * SROW * 2) + koff;
                LDSM4(bfr[2 * p][0], bfr[2 * p + 1][0], bfr[2 * p][1], bfr[2 * p + 1][1],
                      sb + toff);
            }
#pragma unroll
            for (int mt = 0; mt < 2; mt++)
#pragma unroll
                for (int nt = 0; nt < 8; nt++)
                    MMA_BF16(acc[mt][nt], af[mt], bfr[nt]);
        }
    }

    // epilogue: write relu(acc + bias); accumulate per-column stats
    float cs[8][2], cq[8][2];
#pragma unroll
    for (int nt = 0; nt < 8; nt++) {
        cs[nt][0] = cs[nt][1] = 0.f;
        cq[nt][0] = cq[nt][1] = 0.f;
    }
#pragma unroll
    for (int mt = 0; mt < 2; mt++) {
        int gr0 = m0 + wm * 32 + mt * 16 + lq;
        int gr1 = gr0 + 8;
#pragma unroll
        for (int nt = 0; nt < 8; nt++) {
            int gc = n0 + wn * 64 + nt * 8 + lr;
            float2 bv = *(const float2*)&bias[gc];
            if (gr0 < N_NODES) {
                float ox = fmaxf(acc[mt][nt][0] + bv.x, 0.f);
                float oy = fmaxf(acc[mt][nt][1] + bv.y, 0.f);
                float2 o0 = {ox, oy};
                *(float2*)&out[(long)gr0 * D + gc] = o0;
                cs[nt][0] += ox; cq[nt][0] += ox * ox;
                cs[nt][1] += oy; cq[nt][1] += oy * oy;
            }
            if (gr1 < N_NODES) {
                float ox = fmaxf(acc[mt][nt][2] + bv.x, 0.f);
                float oy = fmaxf(acc[mt][nt][3] + bv.y, 0.f);
                float2 o1 = {ox, oy};
                *(float2*)&out[(long)gr1 * D + gc] = o1;
                cs[nt][0] += ox; cq[nt][0] += ox * ox;
                cs[nt][1] += oy; cq[nt][1] += oy * oy;
            }
        }
    }
    if (do_stats) {
#pragma unroll
        for (int nt = 0; nt < 8; nt++) {
#pragma unroll
            for (int p = 0; p < 2; p++) {
                float s = cs[nt][p], q = cq[nt][p];
                s += __shfl_down_sync(0xFFFFFFFFu, s, 16);
                q += __shfl_down_sync(0xFFFFFFFFu, q, 16);
                s += __shfl_down_sync(0xFFFFFFFFu, s, 8);
                q += __shfl_down_sync(0xFFFFFFFFu, q, 8);
                s += __shfl_down_sync(0xFFFFFFFFu, s, 4);
                q += __shfl_down_sync(0xFFFFFFFFu, q, 4);
                if (lane < 4) {
                    int gc = n0 + wn * 64 + nt * 8 + lane * 2 + p;
                    atomicAdd(&g_sum[gc], s);
                    atomicAdd(&g_sumsq[gc], q);
                }
            }
        }
    }
}

// ---------------- launch ----------------
extern "C" void kernel_launch(void* const* d_in, const int* in_sizes, int n_in,
                              void* d_out, int out_size) {
    const float* x_in  = (const float*)d_in[0];
    const void*  src   = d_in[1];
    const void*  dst   = d_in[2];
    const float* gamma = (const float*)d_in[3];
    const float* beta  = (const float*)d_in[4];
    const float* W     = (const float*)d_in[5];
    const float* bias  = (const float*)d_in[6];
    float* out = (float*)d_out;
    int E = in_sizes[1];

    float *p_xa, *p_xb;
    bf16 *p_Wint;
    cudaGetSymbolAddress((void**)&p_xa, g_xa);
    cudaGetSymbolAddress((void**)&p_xb, g_xb);
    cudaGetSymbolAddress((void**)&p_Wint, g_Wint);

    cudaFuncSetAttribute(mma_gemm_kernel,
                         cudaFuncAttributeMaxDynamicSharedMemorySize, GSMEM_TOT);

    dim3 ggrid(D / 128, N_PAD / 128);

    // setup — index 3 (profiled slot) = layer-0 stats
    zero_setup_kernel<<<(N_NODES + 255) / 256, 256>>>();                 // 0
    zero_sums_kernel<<<1, 512>>>();                                      // 1
    detect_idx_kernel<<<1, 256>>>(src);                                  // 2
    stats_kernel<<<STATS_BLOCKS, 256>>>(x_in);                           // 3 (profiled)
    degree_kernel<<<(E + 255) / 256, 256>>>(src, dst, E);                // 4
    scan_kernel<<<1, 1024>>>();                                          // 5
    csr_fill_kernel<<<(E + 255) / 256, 256>>>(src, dst, E);              // 6
    {
        dim3 wg(D / 32, D / 32, NLAYERS);
        dim3 wb(32, 32);
        wconv_kernel<<<wg, wb>>>(W);                                     // 7
    }

    const float* cur = x_in;
    for (int l = 0; l < NLAYERS; l++) {
        float* nxt = (l == NLAYERS - 1) ? out : ((l & 1) ? p_xb : p_xa);
        int fuse = (l < NLAYERS - 1) ? 1 : 0;
        gather_kernel<<<(N_NODES * 32 + 255) / 256, 256>>>(cur, gamma + l * D, beta + l * D);
        if (fuse) zero_sums_kernel<<<1, 512>>>();   // sums for layer l+1
        mma_gemm_kernel<<<ggrid, 256, GSMEM_TOT>>>(
            p_Wint + (long)l * D * KP, bias + l * D, nxt, fuse);
        cur = nxt;
    }
}

// round 14
// speedup vs baseline: 1.1986x; 1.0421x over previous
#include <cuda_runtime.h>
#include <cuda_bf16.h>
#include <cstdint>

#define N_NODES 10000
#define N_PAD   10112   /* 79 * 128 */
#define D 512
#define EPS 1e-5f
#define NLAYERS 3
#define E_MAX 262144

typedef __nv_bfloat16 bf16;

// ---------------- scratch (static device globals; no allocs) ----------------
__device__ float g_xa[N_NODES * D];    // layer ping
__device__ float g_xb[N_NODES * D];    // layer pong
__device__ bf16  g_Ahi[N_PAD * D];     // gathered features hi (pad rows stay 0)
__device__ bf16  g_Alo[N_PAD * D];     // gathered features lo
__device__ bf16  g_Wthi[NLAYERS * D * D];  // W^T hi [l][n][k]
__device__ bf16  g_Wtlo[NLAYERS * D * D];  // W^T lo
__device__ float g_outdeg[N_NODES];
__device__ int   g_indeg_i[N_NODES];
__device__ float g_srcnorm[N_NODES];
__device__ float g_dstnorm[N_NODES];
__device__ float g_s0[N_NODES];        // sum of srcnorm over in-neighbors
__device__ float g_sum[D];
__device__ float g_sumsq[D];
__device__ int   g_csr_off[N_NODES + 1];
__device__ int   g_cursor[N_NODES];
__device__ int   g_esrc[E_MAX];
__device__ int   g_is64;

// ---------------- PTX helpers ----------------
__device__ __forceinline__ uint32_t smem_u32(const void* p) {
    uint32_t a;
    asm("{ .reg .u64 t; cvta.to.shared.u64 t, %1; cvt.u32.u64 %0, t; }" : "=r"(a) : "l"(p));
    return a;
}
#define CP16(s, g) asm volatile("cp.async.cg.shared.global [%0], [%1], 16;" :: "r"(s), "l"(g) : "memory")
#define CP_COMMIT() asm volatile("cp.async.commit_group;" ::: "memory")
#define CP_WAIT2()  asm volatile("cp.async.wait_group 2;" ::: "memory")
#define MMA_BF16(acc, a, b)                                                           \
    asm volatile("mma.sync.aligned.m16n8k16.row.col.f32.bf16.bf16.f32 "               \
        "{%0,%1,%2,%3},{%4,%5,%6,%7},{%8,%9},{%0,%1,%2,%3};"                          \
        : "+f"((acc)[0]), "+f"((acc)[1]), "+f"((acc)[2]), "+f"((acc)[3])              \
        : "r"((a)[0]), "r"((a)[1]), "r"((a)[2]), "r"((a)[3]),                         \
          "r"((b)[0]), "r"((b)[1]))
#define LDSM4(r0, r1, r2, r3, addr)                                                   \
    asm volatile("ldmatrix.sync.aligned.m8n8.x4.shared.b16 {%0,%1,%2,%3}, [%4];"      \
        : "=r"(r0), "=r"(r1), "=r"(r2), "=r"(r3) : "r"(addr))

__device__ __forceinline__ int loadIdx(const void* p, int i, int is64) {
    if (is64) return (int)((const long long*)p)[i];
    return ((const int*)p)[i];
}

// ---------------- small kernels ----------------
__global__ void zero_setup_kernel() {
    int i = blockIdx.x * blockDim.x + threadIdx.x;
    if (i < N_NODES) {
        g_outdeg[i] = 0.0f;
        g_indeg_i[i] = 0;
        g_s0[i] = 0.0f;
    }
}
__global__ void zero_sums_kernel() {
    int i = threadIdx.x;        // 512
    g_sum[i] = 0.0f;
    g_sumsq[i] = 0.0f;
}

__global__ void detect_idx_kernel(const void* src) {
    __shared__ int cnt;
    if (threadIdx.x == 0) cnt = 0;
    __syncthreads();
    const int* p = (const int*)src;
    int v = p[2 * threadIdx.x + 1];
    if (v != 0) atomicAdd(&cnt, 1);
    __syncthreads();
    if (threadIdx.x == 0) g_is64 = (cnt == 0) ? 1 : 0;
}

__global__ void degree_kernel(const void* src, const void* dst, int E) {
    int i = blockIdx.x * blockDim.x + threadIdx.x;
    if (i >= E) return;
    int is64 = g_is64;
    int s = loadIdx(src, i, is64);
    int d = loadIdx(dst, i, is64);
    atomicAdd(&g_outdeg[s], 1.0f);
    atomicAdd(&g_indeg_i[d], 1);
}

// single-block scan via warp shuffles + norms
__global__ void scan_kernel() {
    __shared__ int wsum[32];
    const int CH = 10;
    int t = threadIdx.x;
    int lane = t & 31, warp = t >> 5;
    int base = t * CH;
    int loc[CH];
    int tot = 0;
#pragma unroll
    for (int j = 0; j < CH; j++) {
        int i = base + j;
        int d = (i < N_NODES) ? g_indeg_i[i] : 0;
        loc[j] = tot;
        tot += d;
    }
    int inc = tot;
#pragma unroll
    for (int d = 1; d < 32; d <<= 1) {
        int v = __shfl_up_sync(0xFFFFFFFFu, inc, d);
        if (lane >= d) inc += v;
    }
    if (lane == 31) wsum[warp] = inc;
    __syncthreads();
    if (warp == 0) {
        int w = wsum[lane];
        int wi = w;
#pragma unroll
        for (int d = 1; d < 32; d <<= 1) {
            int v = __shfl_up_sync(0xFFFFFFFFu, wi, d);
            if (lane >= d) wi += v;
        }
        wsum[lane] = wi - w;
    }
    __syncthreads();
    int excl = wsum[warp] + inc - tot;
#pragma unroll
    for (int j = 0; j < CH; j++) {
        int i = base + j;
        if (i < N_NODES) {
            int o = excl + loc[j];
            g_csr_off[i] = o;
            g_cursor[i] = o;
            g_srcnorm[i] = rsqrtf(fmaxf(g_outdeg[i], 1.0f));
            g_dstnorm[i] = rsqrtf(fmaxf((float)g_indeg_i[i], 1.0f));
        }
    }
    if (t == 1023) g_csr_off[N_NODES] = wsum[31] + inc;
}

__global__ void csr_fill_kernel(const void* src, const void* dst, int E) {
    int i = blockIdx.x * blockDim.x + threadIdx.x;
    if (i >= E) return;
    int is64 = g_is64;
    int s = loadIdx(src, i, is64);
    int d = loadIdx(dst, i, is64);
    int p = atomicAdd(&g_cursor[d], 1);
    g_esrc[p] = s;
    atomicAdd(&g_s0[d], g_srcnorm[s]);
}

// layer-0 column sums: measured-best config (256 x 128)
#define STATS_BLOCKS 256
__global__ __launch_bounds__(128)
void stats_kernel(const float* __restrict__ x) {
    int c4 = threadIdx.x;                  // 0..127 float4 column
    float4 s = make_float4(0, 0, 0, 0);
    float4 q = make_float4(0, 0, 0, 0);
    const float4* xr = (const float4*)x;
#pragma unroll 4
    for (int row = blockIdx.x; row < N_NODES; row += STATS_BLOCKS) {
        float4 v = xr[(long)row * 128 + c4];
        s.x += v.x; s.y += v.y; s.z += v.z; s.w += v.w;
        q.x += v.x * v.x; q.y += v.y * v.y; q.z += v.z * v.z; q.w += v.w * v.w;
    }
    int c = c4 * 4;
    atomicAdd(&g_sum[c + 0], s.x); atomicAdd(&g_sum[c + 1], s.y);
    atomicAdd(&g_sum[c + 2], s.z); atomicAdd(&g_sum[c + 3], s.w);
    atomicAdd(&g_sumsq[c + 0], q.x); atomicAdd(&g_sumsq[c + 1], q.y);
    atomicAdd(&g_sumsq[c + 2], q.z); atomicAdd(&g_sumsq[c + 3], q.w);
}

// gather + fused BN + dst-norm + bf16 hi/lo split
__global__ __launch_bounds__(256)
void gather_kernel(const float* __restrict__ x,
                   const float* __restrict__ gamma,
                   const float* __restrict__ beta) {
    int gw = (blockIdx.x * 256 + threadIdx.x) >> 5;
    if (gw >= N_NODES) return;
    int lane = threadIdx.x & 31;
    int beg = g_csr_off[gw];
    int end = g_csr_off[gw + 1];
    float4 a0 = make_float4(0, 0, 0, 0), a1 = a0, a2 = a0, a3 = a0;
    int e = beg;
    for (; e + 1 < end; e += 2) {
        int s0i = g_esrc[e];
        int s1i = g_esrc[e + 1];
        float n0 = g_srcnorm[s0i];
        float n1 = g_srcnorm[s1i];
        const float4* r0 = (const float4*)&x[(long)s0i * D];
        const float4* r1 = (const float4*)&x[(long)s1i * D];
        float4 v0 = r0[lane], v1 = r0[lane + 32], v2 = r0[lane + 64], v3 = r0[lane + 96];
        float4 w0 = r1[lane], w1 = r1[lane + 32], w2 = r1[lane + 64], w3 = r1[lane + 96];
        a0.x += n0 * v0.x + n1 * w0.x; a0.y += n0 * v0.y + n1 * w0.y;
        a0.z += n0 * v0.z + n1 * w0.z; a0.w += n0 * v0.w + n1 * w0.w;
        a1.x += n0 * v1.x + n1 * w1.x; a1.y += n0 * v1.y + n1 * w1.y;
        a1.z += n0 * v1.z + n1 * w1.z; a1.w += n0 * v1.w + n1 * w1.w;
        a2.x += n0 * v2.x + n1 * w2.x; a2.y += n0 * v2.y + n1 * w2.y;
        a2.z += n0 * v2.z + n1 * w2.z; a2.w += n0 * v2.w + n1 * w2.w;
        a3.x += n0 * v3.x + n1 * w3.x; a3.y += n0 * v3.y + n1 * w3.y;
        a3.z += n0 * v3.z + n1 * w3.z; a3.w += n0 * v3.w + n1 * w3.w;
    }
    if (e < end) {
        int s0i = g_esrc[e];
        float n0 = g_srcnorm[s0i];
        const float4* r0 = (const float4*)&x[(long)s0i * D];
        float4 v0 = r0[lane], v1 = r0[lane + 32], v2 = r0[lane + 64], v3 = r0[lane + 96];
        a0.x += n0 * v0.x; a0.y += n0 * v0.y; a0.z += n0 * v0.z; a0.w += n0 * v0.w;
        a1.x += n0 * v1.x; a1.y += n0 * v1.y; a1.z += n0 * v1.z; a1.w += n0 * v1.w;
        a2.x += n0 * v2.x; a2.y += n0 * v2.y; a2.z += n0 * v2.z; a2.w += n0 * v2.w;
        a3.x += n0 * v3.x; a3.y += n0 * v3.y; a3.z += n0 * v3.z; a3.w += n0 * v3.w;
    }
    float s0 = g_s0[gw];
    float dn = g_dstnorm[gw];
    const float invN = 1.0f / (float)N_NODES;
    float4 av[4] = {a0, a1, a2, a3};
    long rbase = (long)gw * D;
#pragma unroll
    for (int i = 0; i < 4; i++) {
        int c = i * 128 + lane * 4;
        float4 sm4 = *(const float4*)&g_sum[c];
        float4 sq4 = *(const float4*)&g_sumsq[c];
        float4 gm4 = *(const float4*)&gamma[c];
        float4 bt4 = *(const float4*)&beta[c];
        float V[4] = {av[i].x, av[i].y, av[i].z, av[i].w};
        float smv[4] = {sm4.x, sm4.y, sm4.z, sm4.w};
        float sqv[4] = {sq4.x, sq4.y, sq4.z, sq4.w};
        float gmv[4] = {gm4.x, gm4.y, gm4.z, gm4.w};
        float btv[4] = {bt4.x, bt4.y, bt4.z, bt4.w};
        bf16 hi[4], lo[4];
#pragma unroll
        for (int q = 0; q < 4; q++) {
            float mu = smv[q] * invN;
            float var = sqv[q] * invN - mu * mu;
            float sc = rsqrtf(var + EPS) * gmv[q];
            float val = (sc * (V[q] - mu * s0) + btv[q] * s0) * dn;
            hi[q] = __float2bfloat16(val);
            lo[q] = __float2bfloat16(val - __bfloat162float(hi[q]));
        }
        *(uint2*)&g_Ahi[rbase + c] = *(uint2*)hi;
        *(uint2*)&g_Alo[rbase + c] = *(uint2*)lo;
    }
}

// W transpose + bf16 hi/lo split
__global__ void wconv_kernel(const float* __restrict__ W) {
    __shared__ float tile[32][33];
    int l = blockIdx.z;
    int k = blockIdx.y * 32 + threadIdx.y;
    int n = blockIdx.x * 32 + threadIdx.x;
    tile[threadIdx.y][threadIdx.x] = W[(long)l * D * D + k * D + n];
    __syncthreads();
    int on = blockIdx.x * 32 + threadIdx.y;
    int ok = blockIdx.y * 32 + threadIdx.x;
    float v = tile[threadIdx.x][threadIdx.y];
    bf16 hi = __float2bfloat16(v);
    bf16 lo = __float2bfloat16(v - __bfloat162float(hi));
    long o = (long)l * D * D + on * D + ok;
    g_Wthi[o] = hi;
    g_Wtlo[o] = lo;
}

// ---------------- mma.sync bf16 GEMM: 4 mats, BK=16, 4-stage, 1 sync/chunk ----
#define SROW 24                          /* 16 + 8 pad halves; 48B row stride */
#define MAT_BYTES (128 * SROW * 2)       /* 6144 */
#define STAGE_BYTES (4 * MAT_BYTES)      /* 24576: Ahi,Alo,Whi,Wlo */
#define NSTAGE 4
#define GSMEM_TOT (NSTAGE * STAGE_BYTES) /* 98304 */
#define NKC (D / 16)                     /* 32 */

__global__ __launch_bounds__(256)
void mma_gemm_kernel(const bf16* __restrict__ Whi,   // [n][k]
                     const bf16* __restrict__ Wlo,
                     const float* __restrict__ bias,
                     float* __restrict__ out,
                     int do_stats) {
    extern __shared__ bf16 sm[];
    uint32_t sbase = smem_u32(sm);
    int tid = threadIdx.x;
    int m0 = blockIdx.y * 128;
    int n0 = blockIdx.x * 128;

    int lane = tid & 31;
    int warp = tid >> 5;
    int wm = warp >> 1;                 // 0..3 (rows, 32 each)
    int wn = warp & 1;                  // 0..1 (cols, 64 each)
    int lq = lane >> 2;                 // 0..7
    int lr = (lane & 3) * 2;            // 0,2,4,6

    int lrow = lane & 15;
    int lcol8 = (lane >> 4) << 3;
    uint32_t a_lane_off = (uint32_t)(((wm * 32 + lrow) * SROW + lcol8) * 2);
    uint32_t b_lane_off = (uint32_t)(((wn * 64 + lrow) * SROW + lcol8) * 2);

    // global load: thread -> (row = tid>>1, one 16B seg per matrix)
    int ldr = tid >> 1;                 // 0..127
    int seg0 = (tid & 1);               // 0 or 1 (16B seg within 32B row-chunk)

    const bf16* gAhi = &g_Ahi[(long)(m0 + ldr) * D];
    const bf16* gAlo = &g_Alo[(long)(m0 + ldr) * D];
    const bf16* gBhi = &Whi[(long)(n0 + ldr) * D];
    const bf16* gBlo = &Wlo[(long)(n0 + ldr) * D];
    uint32_t srow_off = (uint32_t)(ldr * SROW * 2 + seg0 * 16);

    float acc[2][8][4];
#pragma unroll
    for (int mt = 0; mt < 2; mt++)
#pragma unroll
        for (int nt = 0; nt < 8; nt++)
#pragma unroll
            for (int q = 0; q < 4; q++) acc[mt][nt][q] = 0.f;

#define ISSUE_CHUNK(kc, st) do {                                                      \
    uint32_t _b = sbase + (uint32_t)(st) * STAGE_BYTES + srow_off;                    \
    int _go = (kc) * 16 + seg0 * 8;                                                   \
    CP16(_b + 0 * MAT_BYTES, (const char*)(gAhi + _go));                              \
    CP16(_b + 1 * MAT_BYTES, (const char*)(gAlo + _go));                              \
    CP16(_b + 2 * MAT_BYTES, (const char*)(gBhi + _go));                              \
    CP16(_b + 3 * MAT_BYTES, (const char*)(gBlo + _go));                              \
    CP_COMMIT();                                                                      \
} while (0)

    ISSUE_CHUNK(0, 0);
    ISSUE_CHUNK(1, 1);
    ISSUE_CHUNK(2, 2);

    for (int kc = 0; kc < NKC; kc++) {
        CP_WAIT2();
        __syncthreads();
        if (kc + 3 < NKC) ISSUE_CHUNK(kc + 3, (kc + 3) & 3);

        int st = kc & 3;
        uint32_t sa_hi = sbase + st * STAGE_BYTES + 0 * MAT_BYTES + a_lane_off;
        uint32_t sa_lo = sbase + st * STAGE_BYTES + 1 * MAT_BYTES + a_lane_off;
        uint32_t sb_hi = sbase + st * STAGE_BYTES + 2 * MAT_BYTES + b_lane_off;
        uint32_t sb_lo = sbase + st * STAGE_BYTES + 3 * MAT_BYTES + b_lane_off;

        uint32_t ah[2][4], al[2][4], bh[8][2], bl[8][2];
#pragma unroll
        for (int mt = 0; mt < 2; mt++) {
            uint32_t toff = (uint32_t)(mt * 16 * SROW * 2);
            LDSM4(ah[mt][0], ah[mt][1], ah[mt][2], ah[mt][3], sa_hi + toff);
            LDSM4(al[mt][0], al[mt][1], al[mt][2], al[mt][3], sa_lo + toff);
        }
#pragma unroll
        for (int p = 0; p < 4; p++) {
            uint32_t toff = (uint32_t)(p * 16 * SROW * 2);
            LDSM4(bh[2 * p][0], bh[2 * p + 1][0], bh[2 * p][1], bh[2 * p + 1][1],
                  sb_hi + toff);
            LDSM4(bl[2 * p][0], bl[2 * p + 1][0], bl[2 * p][1], bl[2 * p + 1][1],
                  sb_lo + toff);
        }
#pragma unroll
        for (int mt = 0; mt < 2; mt++)
#pragma unroll
            for (int nt = 0; nt < 8; nt++) {
                MMA_BF16(acc[mt][nt], ah[mt], bh[nt]);
                MMA_BF16(acc[mt][nt], ah[mt], bl[nt]);
                MMA_BF16(acc[mt][nt], al[mt], bh[nt]);
            }
    }

    // epilogue: write relu(acc + bias); accumulate per-column stats
    float cs[8][2], cq[8][2];
#pragma unroll
    for (int nt = 0; nt < 8; nt++) {
        cs[nt][0] = cs[nt][1] = 0.f;
        cq[nt][0] = cq[nt][1] = 0.f;
    }
#pragma unroll
    for (int mt = 0; mt < 2; mt++) {
        int gr0 = m0 + wm * 32 + mt * 16 + lq;
        int gr1 = gr0 + 8;
#pragma unroll
        for (int nt = 0; nt < 8; nt++) {
            int gc = n0 + wn * 64 + nt * 8 + lr;
            float2 bv = *(const float2*)&bias[gc];
            if (gr0 < N_NODES) {
                float ox = fmaxf(acc[mt][nt][0] + bv.x, 0.f);
                float oy = fmaxf(acc[mt][nt][1] + bv.y, 0.f);
                float2 o0 = {ox, oy};
                *(float2*)&out[(long)gr0 * D + gc] = o0;
                cs[nt][0] += ox; cq[nt][0] += ox * ox;
                cs[nt][1] += oy; cq[nt][1] += oy * oy;
            }
            if (gr1 < N_NODES) {
                float ox = fmaxf(acc[mt][nt][2] + bv.x, 0.f);
                float oy = fmaxf(acc[mt][nt][3] + bv.y, 0.f);
                float2 o1 = {ox, oy};
                *(float2*)&out[(long)gr1 * D + gc] = o1;
                cs[nt][0] += ox; cq[nt][0] += ox * ox;
                cs[nt][1] += oy; cq[nt][1] += oy * oy;
            }
        }
    }
    if (do_stats) {
#pragma unroll
        for (int nt = 0; nt < 8; nt++) {
#pragma unroll
            for (int p = 0; p < 2; p++) {
                float s = cs[nt][p], q = cq[nt][p];
                s += __shfl_down_sync(0xFFFFFFFFu, s, 16);
                q += __shfl_down_sync(0xFFFFFFFFu, q, 16);
                s += __shfl_down_sync(0xFFFFFFFFu, s, 8);
                q += __shfl_down_sync(0xFFFFFFFFu, q, 8);
                s += __shfl_down_sync(0xFFFFFFFFu, s, 4);
                q += __shfl_down_sync(0xFFFFFFFFu, q, 4);
                if (lane < 4) {
                    int gc = n0 + wn * 64 + nt * 8 + lane * 2 + p;
                    atomicAdd(&g_sum[gc], s);
                    atomicAdd(&g_sumsq[gc], q);
                }
            }
        }
    }
}

// ---------------- launch ----------------
extern "C" void kernel_launch(void* const* d_in, const int* in_sizes, int n_in,
                              void* d_out, int out_size) {
    const float* x_in  = (const float*)d_in[0];
    const void*  src   = d_in[1];
    const void*  dst   = d_in[2];
    const float* gamma = (const float*)d_in[3];
    const float* beta  = (const float*)d_in[4];
    const float* W     = (const float*)d_in[5];
    const float* bias  = (const float*)d_in[6];
    float* out = (float*)d_out;
    int E = in_sizes[1];

    float *p_xa, *p_xb;
    bf16 *p_Wthi, *p_Wtlo;
    cudaGetSymbolAddress((void**)&p_xa, g_xa);
    cudaGetSymbolAddress((void**)&p_xb, g_xb);
    cudaGetSymbolAddress((void**)&p_Wthi, g_Wthi);
    cudaGetSymbolAddress((void**)&p_Wtlo, g_Wtlo);

    cudaFuncSetAttribute(mma_gemm_kernel,
                         cudaFuncAttributeMaxDynamicSharedMemorySize, GSMEM_TOT);

    dim3 ggrid(D / 128, N_PAD / 128);

    // setup — index 3 (profiled slot) = layer-0 stats
    zero_setup_kernel<<<(N_NODES + 255) / 256, 256>>>();                 // 0
    zero_sums_kernel<<<1, 512>>>();                                      // 1
    detect_idx_kernel<<<1, 256>>>(src);                                  // 2
    stats_kernel<<<STATS_BLOCKS, 128>>>(x_in);                           // 3 (profiled)
    degree_kernel<<<(E + 255) / 256, 256>>>(src, dst, E);                // 4
    scan_kernel<<<1, 1024>>>();                                          // 5
    csr_fill_kernel<<<(E + 255) / 256, 256>>>(src, dst, E);              // 6
    {
        dim3 wg(D / 32, D / 32, NLAYERS);
        dim3 wb(32, 32);
        wconv_kernel<<<wg, wb>>>(W);                                     // 7
    }

    const float* cur = x_in;
    for (int l = 0; l < NLAYERS; l++) {
        float* nxt = (l == NLAYERS - 1) ? out : ((l & 1) ? p_xb : p_xa);
        int fuse = (l < NLAYERS - 1) ? 1 : 0;
        gather_kernel<<<(N_NODES * 32 + 255) / 256, 256>>>(cur, gamma + l * D, beta + l * D);
        if (fuse) zero_sums_kernel<<<1, 512>>>();   // sums for layer l+1
        mma_gemm_kernel<<<ggrid, 256, GSMEM_TOT>>>(
            p_Wthi + (long)l * D * D, p_Wtlo + (long)l * D * D,
            bias + l * D, nxt, fuse);
        cur = nxt;
    }
}

// round 16
// speedup vs baseline: 1.5109x; 1.2605x over previous
#include <cuda_runtime.h>
#include <cuda_fp16.h>
#include <cstdint>

#define N_NODES 10000
#define N_PAD   10112   /* 79 * 128 */
#define D 512
#define EPS 1e-5f
#define NLAYERS 3
#define E_MAX 262144

// ---------------- scratch (static device globals; no allocs) ----------------
__device__ float  g_xa[N_NODES * D];   // layer ping
__device__ float  g_xb[N_NODES * D];   // layer pong
__device__ __half g_Ah[N_PAD * D];     // gathered features, fp16 (pad rows stay 0)
__device__ __half g_Wthi[NLAYERS * D * D];  // W^T fp16 hi [l][n][k]
__device__ __half g_Wtlo[NLAYERS * D * D];  // W^T fp16 lo (residual)
__device__ float  g_outdeg[N_NODES];
__device__ int    g_indeg_i[N_NODES];
__device__ float  g_srcnorm[N_NODES];
__device__ float  g_dstnorm[N_NODES];
__device__ float  g_s0[N_NODES];       // sum of srcnorm over in-neighbors
__device__ float  g_sum[D];
__device__ float  g_sumsq[D];
__device__ int    g_csr_off[N_NODES + 1];
__device__ int    g_cursor[N_NODES];
__device__ int    g_esrc[E_MAX];
__device__ int    g_is64;

// ---------------- PTX helpers ----------------
__device__ __forceinline__ uint32_t smem_u32(const void* p) {
    uint32_t a;
    asm("{ .reg .u64 t; cvta.to.shared.u64 t, %1; cvt.u32.u64 %0, t; }" : "=r"(a) : "l"(p));
    return a;
}
#define CP16(s, g) asm volatile("cp.async.cg.shared.global [%0], [%1], 16;" :: "r"(s), "l"(g) : "memory")
#define CP_COMMIT() asm volatile("cp.async.commit_group;" ::: "memory")
#define CP_WAIT2()  asm volatile("cp.async.wait_group 2;" ::: "memory")
#define MMA_F16(acc, a, b)                                                            \
    asm volatile("mma.sync.aligned.m16n8k16.row.col.f32.f16.f16.f32 "                 \
        "{%0,%1,%2,%3},{%4,%5,%6,%7},{%8,%9},{%0,%1,%2,%3};"                          \
        : "+f"((acc)[0]), "+f"((acc)[1]), "+f"((acc)[2]), "+f"((acc)[3])              \
        : "r"((a)[0]), "r"((a)[1]), "r"((a)[2]), "r"((a)[3]),                         \
          "r"((b)[0]), "r"((b)[1]))
#define LDSM4(r0, r1, r2, r3, addr)                                                   \
    asm volatile("ldmatrix.sync.aligned.m8n8.x4.shared.b16 {%0,%1,%2,%3}, [%4];"      \
        : "=r"(r0), "=r"(r1), "=r"(r2), "=r"(r3) : "r"(addr))

__device__ __forceinline__ int loadIdx(const void* p, int i, int is64) {
    if (is64) return (int)((const long long*)p)[i];
    return ((const int*)p)[i];
}

// ---------------- init: zeros + dtype detect (one launch) ----------------
__global__ void init_kernel(const void* src) {
    int bid = blockIdx.x;
    int tid = threadIdx.x;
    if (bid < 40) {                       // zero role
        int i = bid * 256 + tid;
        if (i < N_NODES) {
            g_outdeg[i] = 0.0f;
            g_indeg_i[i] = 0;
            g_s0[i] = 0.0f;
        }
        if (i < D) {
            g_sum[i] = 0.0f;
            g_sumsq[i] = 0.0f;
        }
    } else {                              // detect role (block 40)
        __shared__ int cnt;
        if (tid == 0) cnt = 0;
        __syncthreads();
        const int* p = (const int*)src;
        int v = p[2 * tid + 1];
        if (v != 0) atomicAdd(&cnt, 1);
        __syncthreads();
        if (tid == 0) g_is64 = (cnt == 0) ? 1 : 0;
    }
}

// ---------------- mega: degree + layer-0 stats + W conversion (one launch) ----
#define DEG_BLOCKS   625                  /* ceil(E_MAX? computed at launch) */
#define STATS_BLOCKS 128
#define WCONV_BLOCKS (16 * 16 * NLAYERS)  /* 768 */

__global__ __launch_bounds__(256)
void mega_kernel(const void* src, const void* dst, int E, int degB,
                 const float* __restrict__ x, const float* __restrict__ W) {
    int bid = blockIdx.x;
    int tid = threadIdx.x;
    if (bid < degB) {
        // --- degree role ---
        int i = bid * 256 + tid;
        if (i < E) {
            int is64 = g_is64;
            int s = loadIdx(src, i, is64);
            int d = loadIdx(dst, i, is64);
            atomicAdd(&g_outdeg[s], 1.0f);
            atomicAdd(&g_indeg_i[d], 1);
        }
    } else if (bid < degB + STATS_BLOCKS) {
        // --- layer-0 stats role: 128 blocks x 256 threads ---
        int sb = bid - degB;
        int c4 = tid & 127;
        int rsub = tid >> 7;              // 0..1
        float4 s = make_float4(0, 0, 0, 0);
        float4 q = make_float4(0, 0, 0, 0);
        const float4* xr = (const float4*)x;
#pragma unroll 4
        for (int row = sb * 2 + rsub; row < N_NODES; row += STATS_BLOCKS * 2) {
            float4 v = xr[(long)row * 128 + c4];
            s.x += v.x; s.y += v.y; s.z += v.z; s.w += v.w;
            q.x += v.x * v.x; q.y += v.y * v.y; q.z += v.z * v.z; q.w += v.w * v.w;
        }
        int c = c4 * 4;
        atomicAdd(&g_sum[c + 0], s.x); atomicAdd(&g_sum[c + 1], s.y);
        atomicAdd(&g_sum[c + 2], s.z); atomicAdd(&g_sum[c + 3], s.w);
        atomicAdd(&g_sumsq[c + 0], q.x); atomicAdd(&g_sumsq[c + 1], q.y);
        atomicAdd(&g_sumsq[c + 2], q.z); atomicAdd(&g_sumsq[c + 3], q.w);
    } else {
        // --- wconv role: one 32x32 tile per block ---
        __shared__ float tile[32][33];
        int wb = bid - degB - STATS_BLOCKS;        // 0..767
        int l = wb >> 8;                           // /256
        int tb = wb & 255;
        int tk0 = (tb >> 4) * 32;                  // k tile
        int tn0 = (tb & 15) * 32;                  // n tile
        int tr = tid >> 5;                         // 0..7
        int tc = tid & 31;
#pragma unroll
        for (int r = 0; r < 4; r++) {
            int kk = tk0 + tr + r * 8;
            tile[tr + r * 8][tc] = W[(long)l * D * D + (long)kk * D + tn0 + tc];
        }
        __syncthreads();
#pragma unroll
        for (int r = 0; r < 4; r++) {
            int on = tn0 + tr + r * 8;
            int ok = tk0 + tc;
            float v = tile[tc][tr + r * 8];
            __half hi = __float2half_rn(v);
            __half lo = __float2half_rn(v - __half2float(hi));
            long o = (long)l * D * D + (long)on * D + ok;
            g_Wthi[o] = hi;
            g_Wtlo[o] = lo;
        }
    }
}

// single-block scan via warp shuffles + norms
__global__ void scan_kernel() {
    __shared__ int wsum[32];
    const int CH = 10;
    int t = threadIdx.x;
    int lane = t & 31, warp = t >> 5;
    int base = t * CH;
    int loc[CH];
    int tot = 0;
#pragma unroll
    for (int j = 0; j < CH; j++) {
        int i = base + j;
        int d = (i < N_NODES) ? g_indeg_i[i] : 0;
        loc[j] = tot;
        tot += d;
    }
    int inc = tot;
#pragma unroll
    for (int d = 1; d < 32; d <<= 1) {
        int v = __shfl_up_sync(0xFFFFFFFFu, inc, d);
        if (lane >= d) inc += v;
    }
    if (lane == 31) wsum[warp] = inc;
    __syncthreads();
    if (warp == 0) {
        int w = wsum[lane];
        int wi = w;
#pragma unroll
        for (int d = 1; d < 32; d <<= 1) {
            int v = __shfl_up_sync(0xFFFFFFFFu, wi, d);
            if (lane >= d) wi += v;
        }
        wsum[lane] = wi - w;
    }
    __syncthreads();
    int excl = wsum[warp] + inc - tot;
#pragma unroll
    for (int j = 0; j < CH; j++) {
        int i = base + j;
        if (i < N_NODES) {
            int o = excl + loc[j];
            g_csr_off[i] = o;
            g_cursor[i] = o;
            g_srcnorm[i] = rsqrtf(fmaxf(g_outdeg[i], 1.0f));
            g_dstnorm[i] = rsqrtf(fmaxf((float)g_indeg_i[i], 1.0f));
        }
    }
    if (t == 1023) g_csr_off[N_NODES] = wsum[31] + inc;
}

__global__ void csr_fill_kernel(const void* src, const void* dst, int E) {
    int i = blockIdx.x * blockDim.x + threadIdx.x;
    if (i >= E) return;
    int is64 = g_is64;
    int s = loadIdx(src, i, is64);
    int d = loadIdx(dst, i, is64);
    int p = atomicAdd(&g_cursor[d], 1);
    g_esrc[p] = s;
    atomicAdd(&g_s0[d], g_srcnorm[s]);
}

__global__ void zero_sums_kernel() {
    int i = threadIdx.x;        // 512
    g_sum[i] = 0.0f;
    g_sumsq[i] = 0.0f;
}

// gather + fused BN + dst-norm + fp16 convert
__global__ __launch_bounds__(256)
void gather_kernel(const float* __restrict__ x,
                   const float* __restrict__ gamma,
                   const float* __restrict__ beta) {
    int gw = (blockIdx.x * 256 + threadIdx.x) >> 5;
    if (gw >= N_NODES) return;
    int lane = threadIdx.x & 31;
    int beg = g_csr_off[gw];
    int end = g_csr_off[gw + 1];
    float4 a0 = make_float4(0, 0, 0, 0), a1 = a0, a2 = a0, a3 = a0;
    int e = beg;
    for (; e + 1 < end; e += 2) {
        int s0i = g_esrc[e];
        int s1i = g_esrc[e + 1];
        float n0 = g_srcnorm[s0i];
        float n1 = g_srcnorm[s1i];
        const float4* r0 = (const float4*)&x[(long)s0i * D];
        const float4* r1 = (const float4*)&x[(long)s1i * D];
        float4 v0 = r0[lane], v1 = r0[lane + 32], v2 = r0[lane + 64], v3 = r0[lane + 96];
        float4 w0 = r1[lane], w1 = r1[lane + 32], w2 = r1[lane + 64], w3 = r1[lane + 96];
        a0.x += n0 * v0.x + n1 * w0.x; a0.y += n0 * v0.y + n1 * w0.y;
        a0.z += n0 * v0.z + n1 * w0.z; a0.w += n0 * v0.w + n1 * w0.w;
        a1.x += n0 * v1.x + n1 * w1.x; a1.y += n0 * v1.y + n1 * w1.y;
        a1.z += n0 * v1.z + n1 * w1.z; a1.w += n0 * v1.w + n1 * w1.w;
        a2.x += n0 * v2.x + n1 * w2.x; a2.y += n0 * v2.y + n1 * w2.y;
        a2.z += n0 * v2.z + n1 * w2.z; a2.w += n0 * v2.w + n1 * w2.w;
        a3.x += n0 * v3.x + n1 * w3.x; a3.y += n0 * v3.y + n1 * w3.y;
        a3.z += n0 * v3.z + n1 * w3.z; a3.w += n0 * v3.w + n1 * w3.w;
    }
    if (e < end) {
        int s0i = g_esrc[e];
        float n0 = g_srcnorm[s0i];
        const float4* r0 = (const float4*)&x[(long)s0i * D];
        float4 v0 = r0[lane], v1 = r0[lane + 32], v2 = r0[lane + 64], v3 = r0[lane + 96];
        a0.x += n0 * v0.x; a0.y += n0 * v0.y; a0.z += n0 * v0.z; a0.w += n0 * v0.w;
        a1.x += n0 * v1.x; a1.y += n0 * v1.y; a1.z += n0 * v1.z; a1.w += n0 * v1.w;
        a2.x += n0 * v2.x; a2.y += n0 * v2.y; a2.z += n0 * v2.z; a2.w += n0 * v2.w;
        a3.x += n0 * v3.x; a3.y += n0 * v3.y; a3.z += n0 * v3.z; a3.w += n0 * v3.w;
    }
    float s0 = g_s0[gw];
    float dn = g_dstnorm[gw];
    const float invN = 1.0f / (float)N_NODES;
    float4 av[4] = {a0, a1, a2, a3};
    long rbase = (long)gw * D;
#pragma unroll
    for (int i = 0; i < 4; i++) {
        int c = i * 128 + lane * 4;
        float4 sm4 = *(const float4*)&g_sum[c];
        float4 sq4 = *(const float4*)&g_sumsq[c];
        float4 gm4 = *(const float4*)&gamma[c];
        float4 bt4 = *(const float4*)&beta[c];
        float V[4] = {av[i].x, av[i].y, av[i].z, av[i].w};
        float smv[4] = {sm4.x, sm4.y, sm4.z, sm4.w};
        float sqv[4] = {sq4.x, sq4.y, sq4.z, sq4.w};
        float gmv[4] = {gm4.x, gm4.y, gm4.z, gm4.w};
        float btv[4] = {bt4.x, bt4.y, bt4.z, bt4.w};
        __half hv[4];
#pragma unroll
        for (int q = 0; q < 4; q++) {
            float mu = smv[q] * invN;
            float var = sqv[q] * invN - mu * mu;
            float sc = rsqrtf(var + EPS) * gmv[q];
            float val = (sc * (V[q] - mu * s0) + btv[q] * s0) * dn;
            hv[q] = __float2half_rn(val);
        }
        *(uint2*)&g_Ah[rbase + c] = *(uint2*)hv;
    }
}

// ---------------- mma.sync fp16 GEMM: 3 mats (A, Whi, Wlo), BK=16, 4-stage ----
#define SROW 24                          /* 16 + 8 pad halves; 48B row stride */
#define MAT_BYTES (128 * SROW * 2)       /* 6144 */
#define STAGE_BYTES (3 * MAT_BYTES)      /* 18432: A, Whi, Wlo */
#define NSTAGE 4
#define GSMEM_TOT (NSTAGE * STAGE_BYTES) /* 73728 -> 3 CTAs/SM */
#define NKC (D / 16)                     /* 32 */

__global__ __launch_bounds__(256)
void mma_gemm_kernel(const __half* __restrict__ Whi,   // [n][k]
                     const __half* __restrict__ Wlo,
                     const float* __restrict__ bias,
                     float* __restrict__ out,
                     int do_stats) {
    extern __shared__ __half sm[];
    uint32_t sbase = smem_u32(sm);
    int tid = threadIdx.x;
    int m0 = blockIdx.y * 128;
    int n0 = blockIdx.x * 128;

    int lane = tid & 31;
    int warp = tid >> 5;
    int wm = warp >> 1;                 // 0..3 (rows, 32 each)
    int wn = warp & 1;                  // 0..1 (cols, 64 each)
    int lq = lane >> 2;                 // 0..7
    int lr = (lane & 3) * 2;            // 0,2,4,6

    int lrow = lane & 15;
    int lcol8 = (lane >> 4) << 3;
    uint32_t a_lane_off = (uint32_t)(((wm * 32 + lrow) * SROW + lcol8) * 2);
    uint32_t b_lane_off = (uint32_t)(((wn * 64 + lrow) * SROW + lcol8) * 2);

    int ldr = tid >> 1;                 // 0..127
    int seg0 = (tid & 1);               // 0 or 1

    const __half* gA   = &g_Ah[(long)(m0 + ldr) * D];
    const __half* gBhi = &Whi[(long)(n0 + ldr) * D];
    const __half* gBlo = &Wlo[(long)(n0 + ldr) * D];
    uint32_t srow_off = (uint32_t)(ldr * SROW * 2 + seg0 * 16);

    float acc[2][8][4];
#pragma unroll
    for (int mt = 0; mt < 2; mt++)
#pragma unroll
        for (int nt = 0; nt < 8; nt++)
#pragma unroll
            for (int q = 0; q < 4; q++) acc[mt][nt][q] = 0.f;

#define ISSUE_CHUNK(kc, st) do {                                                      \
    uint32_t _b = sbase + (uint32_t)(st) * STAGE_BYTES + srow_off;                    \
    int _go = (kc) * 16 + seg0 * 8;                                                   \
    CP16(_b + 0 * MAT_BYTES, (const char*)(gA   + _go));                              \
    CP16(_b + 1 * MAT_BYTES, (const char*)(gBhi + _go));                              \
    CP16(_b + 2 * MAT_BYTES, (const char*)(gBlo + _go));                              \
    CP_COMMIT();                                                                      \
} while (0)

    ISSUE_CHUNK(0, 0);
    ISSUE_CHUNK(1, 1);
    ISSUE_CHUNK(2, 2);

    for (int kc = 0; kc < NKC; kc++) {
        CP_WAIT2();
        __syncthreads();
        if (kc + 3 < NKC) ISSUE_CHUNK(kc + 3, (kc + 3) & 3);

        int st = kc & 3;
        uint32_t sa    = sbase + st * STAGE_BYTES + 0 * MAT_BYTES + a_lane_off;
        uint32_t sb_hi = sbase + st * STAGE_BYTES + 1 * MAT_BYTES + b_lane_off;
        uint32_t sb_lo = sbase + st * STAGE_BYTES + 2 * MAT_BYTES + b_lane_off;

        uint32_t ah[2][4], bh[8][2], bl[8][2];
#pragma unroll
        for (int mt = 0; mt < 2; mt++) {
            uint32_t toff = (uint32_t)(mt * 16 * SROW * 2);
            LDSM4(ah[mt][0], ah[mt][1], ah[mt][2], ah[mt][3], sa + toff);
        }
#pragma unroll
        for (int p = 0; p < 4; p++) {
            uint32_t toff = (uint32_t)(p * 16 * SROW * 2);
            LDSM4(bh[2 * p][0], bh[2 * p + 1][0], bh[2 * p][1], bh[2 * p + 1][1],
                  sb_hi + toff);
            LDSM4(bl[2 * p][0], bl[2 * p + 1][0], bl[2 * p][1], bl[2 * p + 1][1],
                  sb_lo + toff);
        }
#pragma unroll
        for (int mt = 0; mt < 2; mt++)
#pragma unroll
            for (int nt = 0; nt < 8; nt++) {
                MMA_F16(acc[mt][nt], ah[mt], bh[nt]);
                MMA_F16(acc[mt][nt], ah[mt], bl[nt]);
            }
    }

    // epilogue: write relu(acc + bias); accumulate per-column stats
    float cs[8][2], cq[8][2];
#pragma unroll
    for (int nt = 0; nt < 8; nt++) {
        cs[nt][0] = cs[nt][1] = 0.f;
        cq[nt][0] = cq[nt][1] = 0.f;
    }
#pragma unroll
    for (int mt = 0; mt < 2; mt++) {
        int gr0 = m0 + wm * 32 + mt * 16 + lq;
        int gr1 = gr0 + 8;
#pragma unroll
        for (int nt = 0; nt < 8; nt++) {
            int gc = n0 + wn * 64 + nt * 8 + lr;
            float2 bv = *(const float2*)&bias[gc];
            if (gr0 < N_NODES) {
                float ox = fmaxf(acc[mt][nt][0] + bv.x, 0.f);
                float oy = fmaxf(acc[mt][nt][1] + bv.y, 0.f);
                float2 o0 = {ox, oy};
                *(float2*)&out[(long)gr0 * D + gc] = o0;
                cs[nt][0] += ox; cq[nt][0] += ox * ox;
                cs[nt][1] += oy; cq[nt][1] += oy * oy;
            }
            if (gr1 < N_NODES) {
                float ox = fmaxf(acc[mt][nt][2] + bv.x, 0.f);
                float oy = fmaxf(acc[mt][nt][3] + bv.y, 0.f);
                float2 o1 = {ox, oy};
                *(float2*)&out[(long)gr1 * D + gc] = o1;
                cs[nt][0] += ox; cq[nt][0] += ox * ox;
                cs[nt][1] += oy; cq[nt][1] += oy * oy;
            }
        }
    }
    if (do_stats) {
#pragma unroll
        for (int nt = 0; nt < 8; nt++) {
#pragma unroll
            for (int p = 0; p < 2; p++) {
                float s = cs[nt][p], q = cq[nt][p];
                s += __shfl_down_sync(0xFFFFFFFFu, s, 16);
                q += __shfl_down_sync(0xFFFFFFFFu, q, 16);
                s += __shfl_down_sync(0xFFFFFFFFu, s, 8);
                q += __shfl_down_sync(0xFFFFFFFFu, q, 8);
                s += __shfl_down_sync(0xFFFFFFFFu, s, 4);
                q += __shfl_down_sync(0xFFFFFFFFu, q, 4);
                if (lane < 4) {
                    int gc = n0 + wn * 64 + nt * 8 + lane * 2 + p;
                    atomicAdd(&g_sum[gc], s);
                    atomicAdd(&g_sumsq[gc], q);
                }
            }
        }
    }
}

// ---------------- launch ----------------
extern "C" void kernel_launch(void* const* d_in, const int* in_sizes, int n_in,
                              void* d_out, int out_size) {
    const float* x_in  = (const float*)d_in[0];
    const void*  src   = d_in[1];
    const void*  dst   = d_in[2];
    const float* gamma = (const float*)d_in[3];
    const float* beta  = (const float*)d_in[4];
    const float* W     = (const float*)d_in[5];
    const float* bias  = (const float*)d_in[6];
    float* out = (float*)d_out;
    int E = in_sizes[1];

    float *p_xa, *p_xb;
    __half *p_Wthi, *p_Wtlo;
    cudaGetSymbolAddress((void**)&p_xa, g_xa);
    cudaGetSymbolAddress((void**)&p_xb, g_xb);
    cudaGetSymbolAddress((void**)&p_Wthi, g_Wthi);
    cudaGetSymbolAddress((void**)&p_Wtlo, g_Wtlo);

    cudaFuncSetAttribute(mma_gemm_kernel,
                         cudaFuncAttributeMaxDynamicSharedMemorySize, GSMEM_TOT);

    dim3 ggrid(D / 128, N_PAD / 128);
    int degB = (E + 255) / 256;

    init_kernel<<<41, 256>>>(src);                                       // 0
    mega_kernel<<<degB + STATS_BLOCKS + WCONV_BLOCKS, 256>>>(            // 1
        src, dst, E, degB, x_in, W);
    scan_kernel<<<1, 1024>>>();                                          // 2
    csr_fill_kernel<<<degB, 256>>>(src, dst, E);                         // 3 (profiled)

    const float* cur = x_in;
    for (int l = 0; l < NLAYERS; l++) {
        float* nxt = (l == NLAYERS - 1) ? out : ((l & 1) ? p_xb : p_xa);
        int fuse = (l < NLAYERS - 1) ? 1 : 0;
        gather_kernel<<<(N_NODES * 32 + 255) / 256, 256>>>(cur, gamma + l * D, beta + l * D);
        if (fuse) zero_sums_kernel<<<1, 512>>>();   // sums for layer l+1
        mma_gemm_kernel<<<ggrid, 256, GSMEM_TOT>>>(
            p_Wthi + (long)l * D * D, p_Wtlo + (long)l * D * D,
            bias + l * D, nxt, fuse);
        cur = nxt;
    }
}

// round 17
// speedup vs baseline: 1.6339x; 1.0814x over previous
#include <cuda_runtime.h>
#include <cuda_fp16.h>
#include <cstdint>

#define N_NODES 10000
#define N_PAD   10112   /* 79 * 128 */
#define D 512
#define EPS 1e-5f
#define NLAYERS 3
#define E_MAX 262144

// ---------------- scratch (static device globals; no allocs) ----------------
__device__ __half g_hx[N_NODES * D];   // intermediate activations, fp16
__device__ __half g_Ah[N_PAD * D];     // gathered features, fp16 (pad rows stay 0)
__device__ __half g_Wthi[NLAYERS * D * D];  // W^T fp16 hi [l][n][k]
__device__ __half g_Wtlo[NLAYERS * D * D];  // W^T fp16 lo (residual)
__device__ float  g_outdeg[N_NODES];
__device__ int    g_indeg_i[N_NODES];
__device__ float  g_srcnorm[N_NODES];
__device__ float  g_dstnorm[N_NODES];
__device__ float  g_s0[N_NODES];       // sum of srcnorm over in-neighbors
__device__ float  g_sum[D];
__device__ float  g_sumsq[D];
__device__ int    g_csr_off[N_NODES + 1];
__device__ int    g_cursor[N_NODES];
__device__ int    g_esrc[E_MAX];
__device__ int    g_is64;

// ---------------- PTX helpers ----------------
__device__ __forceinline__ uint32_t smem_u32(const void* p) {
    uint32_t a;
    asm("{ .reg .u64 t; cvta.to.shared.u64 t, %1; cvt.u32.u64 %0, t; }" : "=r"(a) : "l"(p));
    return a;
}
#define CP16(s, g) asm volatile("cp.async.cg.shared.global [%0], [%1], 16;" :: "r"(s), "l"(g) : "memory")
#define CP_COMMIT() asm volatile("cp.async.commit_group;" ::: "memory")
#define CP_WAIT2()  asm volatile("cp.async.wait_group 2;" ::: "memory")
#define MMA_F16(acc, a, b)                                                            \
    asm volatile("mma.sync.aligned.m16n8k16.row.col.f32.f16.f16.f32 "                 \
        "{%0,%1,%2,%3},{%4,%5,%6,%7},{%8,%9},{%0,%1,%2,%3};"                          \
        : "+f"((acc)[0]), "+f"((acc)[1]), "+f"((acc)[2]), "+f"((acc)[3])              \
        : "r"((a)[0]), "r"((a)[1]), "r"((a)[2]), "r"((a)[3]),                         \
          "r"((b)[0]), "r"((b)[1]))
#define LDSM4(r0, r1, r2, r3, addr)                                                   \
    asm volatile("ldmatrix.sync.aligned.m8n8.x4.shared.b16 {%0,%1,%2,%3}, [%4];"      \
        : "=r"(r0), "=r"(r1), "=r"(r2), "=r"(r3) : "r"(addr))

__device__ __forceinline__ int loadIdx(const void* p, int i, int is64) {
    if (is64) return (int)((const long long*)p)[i];
    return ((const int*)p)[i];
}

// ---------------- init: zeros + dtype detect (one launch) ----------------
__global__ void init_kernel(const void* src) {
    int bid = blockIdx.x;
    int tid = threadIdx.x;
    if (bid < 40) {
        int i = bid * 256 + tid;
        if (i < N_NODES) {
            g_outdeg[i] = 0.0f;
            g_indeg_i[i] = 0;
            g_s0[i] = 0.0f;
        }
        if (i < D) {
            g_sum[i] = 0.0f;
            g_sumsq[i] = 0.0f;
        }
    } else {
        __shared__ int cnt;
        if (tid == 0) cnt = 0;
        __syncthreads();
        const int* p = (const int*)src;
        int v = p[2 * tid + 1];
        if (v != 0) atomicAdd(&cnt, 1);
        __syncthreads();
        if (tid == 0) g_is64 = (cnt == 0) ? 1 : 0;
    }
}

// ---------------- mega: degree + layer-0 stats + W conversion (one launch) ----
#define STATS_BLOCKS 128
#define WCONV_BLOCKS (16 * 16 * NLAYERS)  /* 768 */

__global__ __launch_bounds__(256)
void mega_kernel(const void* src, const void* dst, int E, int degB,
                 const float* __restrict__ x, const float* __restrict__ W) {
    int bid = blockIdx.x;
    int tid = threadIdx.x;
    if (bid < degB) {
        int i = bid * 256 + tid;
        if (i < E) {
            int is64 = g_is64;
            int s = loadIdx(src, i, is64);
            int d = loadIdx(dst, i, is64);
            atomicAdd(&g_outdeg[s], 1.0f);
            atomicAdd(&g_indeg_i[d], 1);
        }
    } else if (bid < degB + STATS_BLOCKS) {
        int sb = bid - degB;
        int c4 = tid & 127;
        int rsub = tid >> 7;
        float4 s = make_float4(0, 0, 0, 0);
        float4 q = make_float4(0, 0, 0, 0);
        const float4* xr = (const float4*)x;
#pragma unroll 4
        for (int row = sb * 2 + rsub; row < N_NODES; row += STATS_BLOCKS * 2) {
            float4 v = xr[(long)row * 128 + c4];
            s.x += v.x; s.y += v.y; s.z += v.z; s.w += v.w;
            q.x += v.x * v.x; q.y += v.y * v.y; q.z += v.z * v.z; q.w += v.w * v.w;
        }
        int c = c4 * 4;
        atomicAdd(&g_sum[c + 0], s.x); atomicAdd(&g_sum[c + 1], s.y);
        atomicAdd(&g_sum[c + 2], s.z); atomicAdd(&g_sum[c + 3], s.w);
        atomicAdd(&g_sumsq[c + 0], q.x); atomicAdd(&g_sumsq[c + 1], q.y);
        atomicAdd(&g_sumsq[c + 2], q.z); atomicAdd(&g_sumsq[c + 3], q.w);
    } else {
        __shared__ float tile[32][33];
        int wb = bid - degB - STATS_BLOCKS;
        int l = wb >> 8;
        int tb = wb & 255;
        int tk0 = (tb >> 4) * 32;
        int tn0 = (tb & 15) * 32;
        int tr = tid >> 5;
        int tc = tid & 31;
#pragma unroll
        for (int r = 0; r < 4; r++) {
            int kk = tk0 + tr + r * 8;
            tile[tr + r * 8][tc] = W[(long)l * D * D + (long)kk * D + tn0 + tc];
        }
        __syncthreads();
#pragma unroll
        for (int r = 0; r < 4; r++) {
            int on = tn0 + tr + r * 8;
            int ok = tk0 + tc;
            float v = tile[tc][tr + r * 8];
            __half hi = __float2half_rn(v);
            __half lo = __float2half_rn(v - __half2float(hi));
            long o = (long)l * D * D + (long)on * D + ok;
            g_Wthi[o] = hi;
            g_Wtlo[o] = lo;
        }
    }
}

// single-block scan via warp shuffles + norms
__global__ void scan_kernel() {
    __shared__ int wsum[32];
    const int CH = 10;
    int t = threadIdx.x;
    int lane = t & 31, warp = t >> 5;
    int base = t * CH;
    int loc[CH];
    int tot = 0;
#pragma unroll
    for (int j = 0; j < CH; j++) {
        int i = base + j;
        int d = (i < N_NODES) ? g_indeg_i[i] : 0;
        loc[j] = tot;
        tot += d;
    }
    int inc = tot;
#pragma unroll
    for (int d = 1; d < 32; d <<= 1) {
        int v = __shfl_up_sync(0xFFFFFFFFu, inc, d);
        if (lane >= d) inc += v;
    }
    if (lane == 31) wsum[warp] = inc;
    __syncthreads();
    if (warp == 0) {
        int w = wsum[lane];
        int wi = w;
#pragma unroll
        for (int d = 1; d < 32; d <<= 1) {
            int v = __shfl_up_sync(0xFFFFFFFFu, wi, d);
            if (lane >= d) wi += v;
        }
        wsum[lane] = wi - w;
    }
    __syncthreads();
    int excl = wsum[warp] + inc - tot;
#pragma unroll
    for (int j = 0; j < CH; j++) {
        int i = base + j;
        if (i < N_NODES) {
            int o = excl + loc[j];
            g_csr_off[i] = o;
            g_cursor[i] = o;
            g_srcnorm[i] = rsqrtf(fmaxf(g_outdeg[i], 1.0f));
            g_dstnorm[i] = rsqrtf(fmaxf((float)g_indeg_i[i], 1.0f));
        }
    }
    if (t == 1023) g_csr_off[N_NODES] = wsum[31] + inc;
}

__global__ void csr_fill_kernel(const void* src, const void* dst, int E) {
    int i = blockIdx.x * blockDim.x + threadIdx.x;
    if (i >= E) return;
    int is64 = g_is64;
    int s = loadIdx(src, i, is64);
    int d = loadIdx(dst, i, is64);
    int p = atomicAdd(&g_cursor[d], 1);
    g_esrc[p] = s;
    atomicAdd(&g_s0[d], g_srcnorm[s]);
}

__global__ void zero_sums_kernel() {
    int i = threadIdx.x;        // 512
    g_sum[i] = 0.0f;
    g_sumsq[i] = 0.0f;
}

// finalize of gather: BN + dst-norm + fp16 convert + store to g_Ah
__device__ __forceinline__ void gather_store(
    int gw, int lane, const float* V16,           // 16 values: cols c0..c0+7, c1..c1+7
    int c0, int c1,
    const float* __restrict__ gamma, const float* __restrict__ beta) {
    float s0 = g_s0[gw];
    float dn = g_dstnorm[gw];
    const float invN = 1.0f / (float)N_NODES;
    long rbase = (long)gw * D;
#pragma unroll
    for (int h = 0; h < 2; h++) {
        int c = h ? c1 : c0;
        __half hv[8];
#pragma unroll
        for (int q8 = 0; q8 < 2; q8++) {
            int cc = c + q8 * 4;
            float4 sm4 = *(const float4*)&g_sum[cc];
            float4 sq4 = *(const float4*)&g_sumsq[cc];
            float4 gm4 = *(const float4*)&gamma[cc];
            float4 bt4 = *(const float4*)&beta[cc];
            float smv[4] = {sm4.x, sm4.y, sm4.z, sm4.w};
            float sqv[4] = {sq4.x, sq4.y, sq4.z, sq4.w};
            float gmv[4] = {gm4.x, gm4.y, gm4.z, gm4.w};
            float btv[4] = {bt4.x, bt4.y, bt4.z, bt4.w};
#pragma unroll
            for (int q = 0; q < 4; q++) {
                float mu = smv[q] * invN;
                float var = sqv[q] * invN - mu * mu;
                float sc = rsqrtf(var + EPS) * gmv[q];
                float val = (sc * (V16[h * 8 + q8 * 4 + q] - mu * s0) + btv[q] * s0) * dn;
                hv[q8 * 4 + q] = __float2half_rn(val);
            }
        }
        *(uint4*)&g_Ah[rbase + c] = *(uint4*)hv;
    }
}

// gather layer 0: reads fp32 input
__global__ __launch_bounds__(256)
void gather_f32_kernel(const float* __restrict__ x,
                       const float* __restrict__ gamma,
                       const float* __restrict__ beta) {
    int gw = (blockIdx.x * 256 + threadIdx.x) >> 5;
    if (gw >= N_NODES) return;
    int lane = threadIdx.x & 31;
    int beg = g_csr_off[gw];
    int end = g_csr_off[gw + 1];
    // lane covers cols [lane*8, lane*8+8) and [256+lane*8, ...+8)
    int c0 = lane * 8, c1 = 256 + lane * 8;
    float A[16];
#pragma unroll
    for (int i = 0; i < 16; i++) A[i] = 0.f;
    int e = beg;
    for (; e + 1 < end; e += 2) {
        int s0i = g_esrc[e];
        int s1i = g_esrc[e + 1];
        float n0 = g_srcnorm[s0i];
        float n1 = g_srcnorm[s1i];
        const float4* r0 = (const float4*)&x[(long)s0i * D];
        const float4* r1 = (const float4*)&x[(long)s1i * D];
        float4 u0 = r0[c0 >> 2], u1 = r0[(c0 >> 2) + 1];
        float4 u2 = r0[c1 >> 2], u3 = r0[(c1 >> 2) + 1];
        float4 w0 = r1[c0 >> 2], w1 = r1[(c0 >> 2) + 1];
        float4 w2 = r1[c1 >> 2], w3 = r1[(c1 >> 2) + 1];
        A[0] += n0 * u0.x + n1 * w0.x;  A[1] += n0 * u0.y + n1 * w0.y;
        A[2] += n0 * u0.z + n1 * w0.z;  A[3] += n0 * u0.w + n1 * w0.w;
        A[4] += n0 * u1.x + n1 * w1.x;  A[5] += n0 * u1.y + n1 * w1.y;
        A[6] += n0 * u1.z + n1 * w1.z;  A[7] += n0 * u1.w + n1 * w1.w;
        A[8] += n0 * u2.x + n1 * w2.x;  A[9] += n0 * u2.y + n1 * w2.y;
        A[10] += n0 * u2.z + n1 * w2.z; A[11] += n0 * u2.w + n1 * w2.w;
        A[12] += n0 * u3.x + n1 * w3.x; A[13] += n0 * u3.y + n1 * w3.y;
        A[14] += n0 * u3.z + n1 * w3.z; A[15] += n0 * u3.w + n1 * w3.w;
    }
    if (e < end) {
        int s0i = g_esrc[e];
        float n0 = g_srcnorm[s0i];
        const float4* r0 = (const float4*)&x[(long)s0i * D];
        float4 u0 = r0[c0 >> 2], u1 = r0[(c0 >> 2) + 1];
        float4 u2 = r0[c1 >> 2], u3 = r0[(c1 >> 2) + 1];
        A[0] += n0 * u0.x;  A[1] += n0 * u0.y;  A[2] += n0 * u0.z;  A[3] += n0 * u0.w;
        A[4] += n0 * u1.x;  A[5] += n0 * u1.y;  A[6] += n0 * u1.z;  A[7] += n0 * u1.w;
        A[8] += n0 * u2.x;  A[9] += n0 * u2.y;  A[10] += n0 * u2.z; A[11] += n0 * u2.w;
        A[12] += n0 * u3.x; A[13] += n0 * u3.y; A[14] += n0 * u3.z; A[15] += n0 * u3.w;
    }
    gather_store(gw, lane, A, c0, c1, gamma, beta);
}

// gather layers 1+: reads fp16 activations (half the traffic)
__global__ __launch_bounds__(256)
void gather_f16_kernel(const float* __restrict__ gamma,
                       const float* __restrict__ beta) {
    int gw = (blockIdx.x * 256 + threadIdx.x) >> 5;
    if (gw >= N_NODES) return;
    int lane = threadIdx.x & 31;
    int beg = g_csr_off[gw];
    int end = g_csr_off[gw + 1];
    int c0 = lane * 8, c1 = 256 + lane * 8;
    float A[16];
#pragma unroll
    for (int i = 0; i < 16; i++) A[i] = 0.f;

#define ACC_EDGE(sidx) do {                                                           \
    float nn = g_srcnorm[sidx];                                                       \
    const uint4* rr = (const uint4*)&g_hx[(long)(sidx) * D];                          \
    uint4 u0 = rr[lane], u1 = rr[lane + 32];                                          \
    const __half2* h0 = (const __half2*)&u0;                                          \
    const __half2* h1 = (const __half2*)&u1;                                          \
    _Pragma("unroll")                                                                 \
    for (int j = 0; j < 4; j++) {                                                     \
        float2 f0 = __half22float2(h0[j]);                                            \
        float2 f1 = __half22float2(h1[j]);                                            \
        A[2 * j] += nn * f0.x;     A[2 * j + 1] += nn * f0.y;                         \
        A[8 + 2 * j] += nn * f1.x; A[8 + 2 * j + 1] += nn * f1.y;                     \
    }                                                                                 \
} while (0)

    int e = beg;
    for (; e + 3 < end; e += 4) {
        int sa = g_esrc[e], sb = g_esrc[e + 1], sc = g_esrc[e + 2], sd = g_esrc[e + 3];
        ACC_EDGE(sa); ACC_EDGE(sb); ACC_EDGE(sc); ACC_EDGE(sd);
    }
    for (; e < end; e++) {
        int sa = g_esrc[e];
        ACC_EDGE(sa);
    }
    gather_store(gw, lane, A, c0, c1, gamma, beta);
}

// ---------------- mma.sync fp16 GEMM: 3 mats (A, Whi, Wlo), BK=16, 4-stage ----
#define SROW 24                          /* 16 + 8 pad halves; 48B row stride */
#define MAT_BYTES (128 * SROW * 2)       /* 6144 */
#define STAGE_BYTES (3 * MAT_BYTES)      /* 18432: A, Whi, Wlo */
#define NSTAGE 4
#define GSMEM_TOT (NSTAGE * STAGE_BYTES) /* 73728 -> 3 CTAs/SM */
#define NKC (D / 16)                     /* 32 */

__global__ __launch_bounds__(256)
void mma_gemm_kernel(const __half* __restrict__ Whi,   // [n][k]
                     const __half* __restrict__ Wlo,
                     const float* __restrict__ bias,
                     float* __restrict__ out,          // fp32 out (final layer)
                     __half* __restrict__ hout,        // fp16 out (intermediate)
                     int do_stats) {
    extern __shared__ __half sm[];
    uint32_t sbase = smem_u32(sm);
    int tid = threadIdx.x;
    int m0 = blockIdx.y * 128;
    int n0 = blockIdx.x * 128;

    int lane = tid & 31;
    int warp = tid >> 5;
    int wm = warp >> 1;                 // 0..3 (rows, 32 each)
    int wn = warp & 1;                  // 0..1 (cols, 64 each)
    int lq = lane >> 2;                 // 0..7
    int lr = (lane & 3) * 2;            // 0,2,4,6

    int lrow = lane & 15;
    int lcol8 = (lane >> 4) << 3;
    uint32_t a_lane_off = (uint32_t)(((wm * 32 + lrow) * SROW + lcol8) * 2);
    uint32_t b_lane_off = (uint32_t)(((wn * 64 + lrow) * SROW + lcol8) * 2);

    int ldr = tid >> 1;                 // 0..127
    int seg0 = (tid & 1);               // 0 or 1

    const __half* gA   = &g_Ah[(long)(m0 + ldr) * D];
    const __half* gBhi = &Whi[(long)(n0 + ldr) * D];
    const __half* gBlo = &Wlo[(long)(n0 + ldr) * D];
    uint32_t srow_off = (uint32_t)(ldr * SROW * 2 + seg0 * 16);

    float acc[2][8][4];
#pragma unroll
    for (int mt = 0; mt < 2; mt++)
#pragma unroll
        for (int nt = 0; nt < 8; nt++)
#pragma unroll
            for (int q = 0; q < 4; q++) acc[mt][nt][q] = 0.f;

#define ISSUE_CHUNK(kc, st) do {                                                      \
    uint32_t _b = sbase + (uint32_t)(st) * STAGE_BYTES + srow_off;                    \
    int _go = (kc) * 16 + seg0 * 8;                                                   \
    CP16(_b + 0 * MAT_BYTES, (const char*)(gA   + _go));                              \
    CP16(_b + 1 * MAT_BYTES, (const char*)(gBhi + _go));                              \
    CP16(_b + 2 * MAT_BYTES, (const char*)(gBlo + _go));                              \
    CP_COMMIT();                                                                      \
} while (0)

    ISSUE_CHUNK(0, 0);
    ISSUE_CHUNK(1, 1);
    ISSUE_CHUNK(2, 2);

    for (int kc = 0; kc < NKC; kc++) {
        CP_WAIT2();
        __syncthreads();
        if (kc + 3 < NKC) ISSUE_CHUNK(kc + 3, (kc + 3) & 3);

        int st = kc & 3;
        uint32_t sa    = sbase + st * STAGE_BYTES + 0 * MAT_BYTES + a_lane_off;
        uint32_t sb_hi = sbase + st * STAGE_BYTES + 1 * MAT_BYTES + b_lane_off;
        uint32_t sb_lo = sbase + st * STAGE_BYTES + 2 * MAT_BYTES + b_lane_off;

        uint32_t ah[2][4], bh[8][2], bl[8][2];
#pragma unroll
        for (int mt = 0; mt < 2; mt++) {
            uint32_t toff = (uint32_t)(mt * 16 * SROW * 2);
            LDSM4(ah[mt][0], ah[mt][1], ah[mt][2], ah[mt][3], sa + toff);
        }
#pragma unroll
        for (int p = 0; p < 4; p++) {
            uint32_t toff = (uint32_t)(p * 16 * SROW * 2);
            LDSM4(bh[2 * p][0], bh[2 * p + 1][0], bh[2 * p][1], bh[2 * p + 1][1],
                  sb_hi + toff);
            LDSM4(bl[2 * p][0], bl[2 * p + 1][0], bl[2 * p][1], bl[2 * p + 1][1],
                  sb_lo + toff);
        }
#pragma unroll
        for (int mt = 0; mt < 2; mt++)
#pragma unroll
            for (int nt = 0; nt < 8; nt++) {
                MMA_F16(acc[mt][nt], ah[mt], bh[nt]);
                MMA_F16(acc[mt][nt], ah[mt], bl[nt]);
            }
    }

    // epilogue: relu(acc + bias) -> fp16 hout (intermediate) or fp32 out (final)
    float cs[8][2], cq[8][2];
#pragma unroll
    for (int nt = 0; nt < 8; nt++) {
        cs[nt][0] = cs[nt][1] = 0.f;
        cq[nt][0] = cq[nt][1] = 0.f;
    }
#pragma unroll
    for (int mt = 0; mt < 2; mt++) {
        int gr0 = m0 + wm * 32 + mt * 16 + lq;
        int gr1 = gr0 + 8;
#pragma unroll
        for (int nt = 0; nt < 8; nt++) {
            int gc = n0 + wn * 64 + nt * 8 + lr;
            float2 bv = *(const float2*)&bias[gc];
            if (gr0 < N_NODES) {
                float ox = fmaxf(acc[mt][nt][0] + bv.x, 0.f);
                float oy = fmaxf(acc[mt][nt][1] + bv.y, 0.f);
                if (hout) {
                    *(__half2*)&hout[(long)gr0 * D + gc] = __floats2half2_rn(ox, oy);
                } else {
                    float2 o0 = {ox, oy};
                    *(float2*)&out[(long)gr0 * D + gc] = o0;
                }
                cs[nt][0] += ox; cq[nt][0] += ox * ox;
                cs[nt][1] += oy; cq[nt][1] += oy * oy;
            }
            if (gr1 < N_NODES) {
                float ox = fmaxf(acc[mt][nt][2] + bv.x, 0.f);
                float oy = fmaxf(acc[mt][nt][3] + bv.y, 0.f);
                if (hout) {
                    *(__half2*)&hout[(long)gr1 * D + gc] = __floats2half2_rn(ox, oy);
                } else {
                    float2 o1 = {ox, oy};
                    *(float2*)&out[(long)gr1 * D + gc] = o1;
                }
                cs[nt][0] += ox; cq[nt][0] += ox * ox;
                cs[nt][1] += oy; cq[nt][1] += oy * oy;
            }
        }
    }
    if (do_stats) {
#pragma unroll
        for (int nt = 0; nt < 8; nt++) {
#pragma unroll
            for (int p = 0; p < 2; p++) {
                float s = cs[nt][p], q = cq[nt][p];
                s += __shfl_down_sync(0xFFFFFFFFu, s, 16);
                q += __shfl_down_sync(0xFFFFFFFFu, q, 16);
                s += __shfl_down_sync(0xFFFFFFFFu, s, 8);
                q += __shfl_down_sync(0xFFFFFFFFu, q, 8);
                s += __shfl_down_sync(0xFFFFFFFFu, s, 4);
                q += __shfl_down_sync(0xFFFFFFFFu, q, 4);
                if (lane < 4) {
                    int gc = n0 + wn * 64 + nt * 8 + lane * 2 + p;
                    atomicAdd(&g_sum[gc], s);
                    atomicAdd(&g_sumsq[gc], q);
                }
            }
        }
    }
}

// ---------------- launch ----------------
extern "C" void kernel_launch(void* const* d_in, const int* in_sizes, int n_in,
                              void* d_out, int out_size) {
    const float* x_in  = (const float*)d_in[0];
    const void*  src   = d_in[1];
    const void*  dst   = d_in[2];
    const float* gamma = (const float*)d_in[3];
    const float* beta  = (const float*)d_in[4];
    const float* W     = (const float*)d_in[5];
    const float* bias  = (const float*)d_in[6];
    float* out = (float*)d_out;
    int E = in_sizes[1];

    __half *p_Wthi, *p_Wtlo, *p_hx;
    cudaGetSymbolAddress((void**)&p_Wthi, g_Wthi);
    cudaGetSymbolAddress((void**)&p_Wtlo, g_Wtlo);
    cudaGetSymbolAddress((void**)&p_hx, g_hx);

    cudaFuncSetAttribute(mma_gemm_kernel,
                         cudaFuncAttributeMaxDynamicSharedMemorySize, GSMEM_TOT);

    dim3 ggrid(D / 128, N_PAD / 128);
    int degB = (E + 255) / 256;
    int gatherB = (N_NODES * 32 + 255) / 256;

    init_kernel<<<41, 256>>>(src);                                       // 0
    mega_kernel<<<degB + STATS_BLOCKS + WCONV_BLOCKS, 256>>>(            // 1
        src, dst, E, degB, x_in, W);
    scan_kernel<<<1, 1024>>>();                                          // 2
    csr_fill_kernel<<<degB, 256>>>(src, dst, E);                         // 3 (profiled)

    for (int l = 0; l < NLAYERS; l++) {
        int fuse = (l < NLAYERS - 1) ? 1 : 0;
        if (l == 0)
            gather_f32_kernel<<<gatherB, 256>>>(x_in, gamma, beta);
        else
            gather_f16_kernel<<<gatherB, 256>>>(gamma + l * D, beta + l * D);
        if (fuse) zero_sums_kernel<<<1, 512>>>();   // sums for layer l+1
        mma_gemm_kernel<<<ggrid, 256, GSMEM_TOT>>>(
            p_Wthi + (long)l * D * D, p_Wtlo + (long)l * D * D,
            bias + l * D,
            fuse ? nullptr : out,
            fuse ? p_hx : nullptr,
            fuse);
    }
}